// round 4
// baseline (speedup 1.0000x reference)
#include <cuda_runtime.h>
#include <cstdint>

#define T_TOK 16384
#define NE 8
#define NK 2

// ---------------- scratch (device globals; no allocation allowed) ----------------
__device__ int   g_maskmode;                 // 1 = mask is 1-byte bool, 0 = int32
__device__ int   g_cnt[3][16];               // per stage, per (slot*8+expert)
__device__ int   g_tok[3][16][T_TOK];
__device__ float g_wgt[3][16][T_TOK];
__device__ float g_h1a[T_TOK * 256];
__device__ float g_h1b[T_TOK * 256];
__device__ float g_h2a[T_TOK * 256];
__device__ float g_h2b[T_TOK * 256];
__device__ float g_h3a[T_TOK * 512];
__device__ float g_h3b[T_TOK * 512];
// fragment-ordered tf32 weights: [e][gstep(IN/8)][ntp(OUT/16)][lane32][4]
__device__ float g_wf1[NE * 64 * 16 * 128];   // stage0: IN=512, OUT=256
__device__ float g_wf2[NE * 32 * 16 * 128];   // stage1: IN=256, OUT=256
__device__ float g_wf3[NE * 32 * 32 * 128];   // stage2: IN=256, OUT=512

// ---------------- helpers ----------------
__device__ __forceinline__ uint32_t f2tf(float f) {
    uint32_t u; asm("cvt.rn.tf32.f32 %0, %1;" : "=r"(u) : "f"(f)); return u;
}

// D = A(16x8,row) * B(8x8,col) + D, tf32 in, f32 accum.
__device__ __forceinline__ void mma8(float* c, const uint32_t* a,
                                     uint32_t b0, uint32_t b1) {
    asm volatile(
        "mma.sync.aligned.m16n8k8.row.col.f32.tf32.tf32.f32 "
        "{%0,%1,%2,%3}, {%4,%5,%6,%7}, {%8,%9}, {%0,%1,%2,%3};"
        : "+f"(c[0]), "+f"(c[1]), "+f"(c[2]), "+f"(c[3])
        : "r"(a[0]), "r"(a[1]), "r"(a[2]), "r"(a[3]), "r"(b0), "r"(b1));
}

// ---------------- weight pre-transform: W[E][OUT][IN] -> fragment order ----------------
template <int IN, int OUT>
__global__ void prep(const float* __restrict__ W, float* __restrict__ WF) {
    int idx = blockIdx.x * blockDim.x + threadIdx.x;   // one uint4 per thread
    constexpr int NTPC = OUT / 16;
    constexpr int GS   = IN / 8;
    if (idx >= NE * GS * NTPC * 32) return;
    int lane = idx & 31;
    int rest = idx >> 5;
    int ntp  = rest % NTPC;
    int gs   = (rest / NTPC) % GS;
    int e    = rest / (NTPC * GS);
    int n0 = ntp * 16 + (lane >> 2);
    int k0 = gs * 8 + (lane & 3);
    const float* We = W + (size_t)e * OUT * IN;
    uint4 v;
    v.x = f2tf(We[(size_t)(n0 + 0) * IN + k0]);
    v.y = f2tf(We[(size_t)(n0 + 0) * IN + k0 + 4]);
    v.z = f2tf(We[(size_t)(n0 + 8) * IN + k0]);
    v.w = f2tf(We[(size_t)(n0 + 8) * IN + k0 + 4]);
    ((uint4*)WF)[idx] = v;
}

// ---------------- mask dtype detection + counter zeroing ----------------
__global__ void detect_and_zero(const unsigned char* __restrict__ m) {
    __shared__ int bad;
    if (threadIdx.x == 0) bad = 0;
    if (threadIdx.x < 48) ((int*)g_cnt)[threadIdx.x] = 0;
    __syncthreads();
    int t = threadIdx.x;
    #pragma unroll
    for (int k = 0; k < NK; k++) {
        int s = 0;
        #pragma unroll
        for (int e = 0; e < NE; e++)
            s += (m[(e * NK + k) * T_TOK + t] != 0) ? 1 : 0;
        if (s != 1) bad = 1;
    }
    __syncthreads();
    if (threadIdx.x == 0) g_maskmode = bad ? 0 : 1;
}

// ---------------- routing ----------------
__global__ void route3(const unsigned char* __restrict__ m1,
                       const unsigned char* __restrict__ m2,
                       const unsigned char* __restrict__ m3,
                       const float* __restrict__ r1,
                       const float* __restrict__ r2,
                       const float* __restrict__ r3) {
    int tid = blockIdx.x * blockDim.x + threadIdx.x;
    if (tid >= 3 * NK * T_TOK) return;
    int s   = tid / (NK * T_TOK);
    int rem = tid % (NK * T_TOK);
    int k   = rem / T_TOK;
    int t   = rem % T_TOK;
    const unsigned char* m = (s == 0) ? m1 : (s == 1) ? m2 : m3;
    const float*         r = (s == 0) ? r1 : (s == 1) ? r2 : r3;

    int e = 0;
    if (g_maskmode) {
        #pragma unroll
        for (int i = 0; i < NE; i++)
            if (m[(i * NK + k) * T_TOK + t]) e = i;
    } else {
        const int* mi = (const int*)m;
        #pragma unroll
        for (int i = 0; i < NE; i++)
            if (mi[(i * NK + k) * T_TOK + t]) e = i;
    }
    float w = r[t * NK + k];
    int g = k * NE + e;
    int p = atomicAdd(&g_cnt[s][g], 1);
    g_tok[s][g][p] = t;
    g_wgt[s][g][p] = w;
}

// ---------------- tf32 mma.sync gathered expert GEMM ----------------
// BM=128, BN=128, BK=16 (2 k8 steps), 256 threads, 8 warps (2m x 4n), warp 64x32.
// A through smem in fragment-native layout; B direct LDG from pre-converted
// fragment-ordered weights (register double-buffered one chunk ahead).
template <int STAGE, int IN, int OUT, bool RELU>
__global__ __launch_bounds__(256, 2)
void moe_mma(const float* __restrict__ X,
             const float* __restrict__ Bias) {
    const float *A0, *A1, *WFg;
    float *O0, *O1;
    if constexpr (STAGE == 0)      { A0 = X;     A1 = nullptr; O0 = g_h1a; O1 = g_h1b; WFg = g_wf1; }
    else if constexpr (STAGE == 1) { A0 = g_h1a; A1 = g_h1b;   O0 = g_h2a; O1 = g_h2b; WFg = g_wf2; }
    else                           { A0 = g_h2a; A1 = g_h2b;   O0 = g_h3a; O1 = g_h3b; WFg = g_wf3; }
    constexpr bool SUMIN = (STAGE != 0);
    constexpr int  NTPC  = OUT / 16;
    constexpr int  GS    = IN / 8;

    const int g  = blockIdx.z;                 // slot*8 + expert
    const int n  = g_cnt[STAGE][g];
    const int m0 = blockIdx.x * 128;
    if (m0 >= n) return;
    const int e  = g & 7;
    const int n0 = blockIdx.y * 128;
    float* Out = (g >= 8) ? O1 : O0;

    // A fragment smem: [buf][step2][tile8][lane32][reg4] floats
    __shared__ float sA[2][2 * 8 * 32 * 4];
    __shared__ int   s_tok[128];
    __shared__ float s_w[128];

    const int tid  = threadIdx.x;
    const int wid  = tid >> 5;
    const int lane = tid & 31;
    const int wm   = wid >> 2;   // 0..1
    const int wn   = wid & 3;    // 0..3

    if (tid < 128) {
        int gi  = m0 + tid;
        int src = (gi < n) ? gi : (n - 1);
        s_tok[tid] = g_tok[STAGE][g][src];
        s_w[tid]   = (gi < n) ? g_wgt[STAGE][g][src] : 0.0f;
    }
    __syncthreads();

    const uint4* WFe = (const uint4*)(WFg + (size_t)e * GS * NTPC * 128);
    const int ntp0 = (n0 >> 4) + wn * 2;

    float c[4][4][4];
    #pragma unroll
    for (int a = 0; a < 4; a++)
        #pragma unroll
        for (int b = 0; b < 4; b++)
            #pragma unroll
            for (int d = 0; d < 4; d++) c[a][b][d] = 0.0f;

    float4 va[2];
    uint4  breg[2][4];    // [buf][step*2 + pair]

    auto LOAD = [&](int kb) {
        #pragma unroll
        for (int it = 0; it < 2; it++) {
            int idx = tid + it * 256;
            int row = idx >> 2;
            int j   = idx & 3;
            int t = s_tok[row];
            float4 v = *(const float4*)(A0 + (size_t)t * IN + kb + j * 4);
            if constexpr (SUMIN) {
                float4 v2 = *(const float4*)(A1 + (size_t)t * IN + kb + j * 4);
                v.x += v2.x; v.y += v2.y; v.z += v2.z; v.w += v2.w;
            }
            va[it] = v;
        }
    };

    auto LDB = [&](int ch, uint4* b) {
        #pragma unroll
        for (int s = 0; s < 2; s++) {
            int gs = ch * 2 + s;
            const uint4* p = WFe + ((size_t)gs * NTPC + ntp0) * 32 + lane;
            b[s * 2 + 0] = p[0];
            b[s * 2 + 1] = p[32];
        }
    };

    auto STS = [&](int buf) {
        #pragma unroll
        for (int it = 0; it < 2; it++) {
            int idx  = tid + it * 256;
            int row  = idx >> 2;
            int j    = idx & 3;
            int step = j >> 1;
            int h    = j & 1;
            int lane0 = 4 * (row & 7);
            uint32_t ua[4] = { f2tf(va[it].x), f2tf(va[it].y),
                               f2tf(va[it].z), f2tf(va[it].w) };
            int mt  = row >> 4;
            int reg = 2 * h + ((row >> 3) & 1);
            float* p = &sA[buf][(step * 8 + mt) * 128 + reg];
            #pragma unroll
            for (int i = 0; i < 4; i++)
                p[((lane0 + i) ^ step) * 4] = __uint_as_float(ua[i]);
        }
    };

    auto COMP = [&](int buf, const uint4* b) {
        const uint4* A4 = (const uint4*)sA[buf];
        #pragma unroll
        for (int s = 0; s < 2; s++) {
            int ls = lane ^ s;
            uint4 a[4];
            #pragma unroll
            for (int mi = 0; mi < 4; mi++)
                a[mi] = A4[(s * 8 + wm * 4 + mi) * 32 + ls];
            #pragma unroll
            for (int mi = 0; mi < 4; mi++) {
                mma8(c[mi][0], (const uint32_t*)&a[mi], b[2 * s].x, b[2 * s].y);
                mma8(c[mi][1], (const uint32_t*)&a[mi], b[2 * s].z, b[2 * s].w);
                mma8(c[mi][2], (const uint32_t*)&a[mi], b[2 * s + 1].x, b[2 * s + 1].y);
                mma8(c[mi][3], (const uint32_t*)&a[mi], b[2 * s + 1].z, b[2 * s + 1].w);
            }
        }
    };

    constexpr int NC = IN / 16;
    LOAD(0);
    LDB(0, breg[0]);
    STS(0);
    __syncthreads();
    for (int ch = 0; ch < NC; ch++) {
        if (ch + 1 < NC) {
            LOAD((ch + 1) * 16);
            LDB(ch + 1, breg[(ch + 1) & 1]);
        }
        COMP(ch & 1, breg[ch & 1]);
        if (ch + 1 < NC) {
            STS((ch + 1) & 1);
            __syncthreads();
        }
    }

    // --- epilogue: bias (+relu) * routing weight, scatter by token ---
    float2 bias[4];
    #pragma unroll
    for (int nt = 0; nt < 4; nt++)
        bias[nt] = *(const float2*)&Bias[e * OUT + n0 + wn * 32 + nt * 8 + (lane & 3) * 2];

    #pragma unroll
    for (int mi = 0; mi < 4; mi++) {
        #pragma unroll
        for (int half = 0; half < 2; half++) {
            int r  = wm * 64 + mi * 16 + (lane >> 2) + half * 8;
            int gi = m0 + r;
            if (gi >= n) continue;
            int   t = s_tok[r];
            float w = s_w[r];
            #pragma unroll
            for (int nt = 0; nt < 4; nt++) {
                float2 v;
                v.x = c[mi][nt][half * 2 + 0] + bias[nt].x;
                v.y = c[mi][nt][half * 2 + 1] + bias[nt].y;
                if constexpr (RELU) {
                    v.x = fmaxf(v.x, 0.0f);
                    v.y = fmaxf(v.y, 0.0f);
                }
                v.x *= w; v.y *= w;
                *(float2*)&Out[(size_t)t * OUT + n0 + wn * 32 + nt * 8 + (lane & 3) * 2] = v;
            }
        }
    }
}

// ---------------- final combine + relu ----------------
__global__ void finalize(float* __restrict__ out) {
    int i = blockIdx.x * blockDim.x + threadIdx.x;
    float4 a = ((const float4*)g_h3a)[i];
    float4 b = ((const float4*)g_h3b)[i];
    float4 v;
    v.x = fmaxf(a.x + b.x, 0.0f);
    v.y = fmaxf(a.y + b.y, 0.0f);
    v.z = fmaxf(a.z + b.z, 0.0f);
    v.w = fmaxf(a.w + b.w, 0.0f);
    ((float4*)out)[i] = v;
}

// ---------------- launch ----------------
extern "C" void kernel_launch(void* const* d_in, const int* in_sizes, int n_in,
                              void* d_out, int out_size) {
    const float*         x  = (const float*)d_in[0];
    const unsigned char* m1 = (const unsigned char*)d_in[1];
    const unsigned char* m2 = (const unsigned char*)d_in[2];
    const unsigned char* m3 = (const unsigned char*)d_in[3];
    const float*         r1 = (const float*)d_in[4];
    const float*         r2 = (const float*)d_in[5];
    const float*         r3 = (const float*)d_in[6];
    const float*         W1 = (const float*)d_in[7];
    const float*         b1 = (const float*)d_in[8];
    const float*         W2 = (const float*)d_in[9];
    const float*         b2 = (const float*)d_in[10];
    const float*         W3 = (const float*)d_in[11];
    const float*         b3 = (const float*)d_in[12];
    float* out = (float*)d_out;

    float *wf1, *wf2, *wf3;
    cudaGetSymbolAddress((void**)&wf1, g_wf1);
    cudaGetSymbolAddress((void**)&wf2, g_wf2);
    cudaGetSymbolAddress((void**)&wf3, g_wf3);

    detect_and_zero<<<1, 256>>>(m1);
    route3<<<(3 * NK * T_TOK + 255) / 256, 256>>>(m1, m2, m3, r1, r2, r3);

    prep<512, 256><<<(NE * 64 * 16 * 32 + 255) / 256, 256>>>(W1, wf1);
    prep<256, 256><<<(NE * 32 * 16 * 32 + 255) / 256, 256>>>(W2, wf2);
    prep<256, 512><<<(NE * 32 * 32 * 32 + 255) / 256, 256>>>(W3, wf3);

    dim3 g1(T_TOK / 128, 256 / 128, 16);
    dim3 g2(T_TOK / 128, 256 / 128, 16);
    dim3 g3(T_TOK / 128, 512 / 128, 16);
    moe_mma<0, 512, 256, false><<<g1, 256>>>(x, b1);
    moe_mma<1, 256, 256, false><<<g2, 256>>>(nullptr, b2);
    moe_mma<2, 256, 512, true ><<<g3, 256>>>(nullptr, b3);

    finalize<<<(T_TOK * 512 / 4) / 256, 256>>>(out);
}

// round 5
// speedup vs baseline: 1.0430x; 1.0430x over previous
#include <cuda_runtime.h>
#include <cstdint>

#define T_TOK 16384
#define NE 8
#define NK 2

// ---------------- scratch (device globals; no allocation allowed) ----------------
__device__ int   g_maskmode;
__device__ int   g_cnt[3][16];
__device__ int   g_tok[3][16][T_TOK];
__device__ float g_wgt[3][16][T_TOK];
__device__ float g_h1a[T_TOK * 256];
__device__ float g_h1b[T_TOK * 256];
__device__ float g_h2a[T_TOK * 256];
__device__ float g_h2b[T_TOK * 256];
__device__ float g_h3a[T_TOK * 512];
__device__ float g_h3b[T_TOK * 512];
// fragment-ordered tf32 weights: [e][gs(IN/8)][ntp(OUT/16)][lane32][4]
__device__ float g_wf1[NE * 64 * 16 * 128];   // stage0: IN=512, OUT=256
__device__ float g_wf2[NE * 32 * 16 * 128];   // stage1: IN=256, OUT=256
__device__ float g_wf3[NE * 32 * 32 * 128];   // stage2: IN=256, OUT=512

// ---------------- helpers ----------------
__device__ __forceinline__ uint32_t f2tf(float f) {
    uint32_t u; asm("cvt.rn.tf32.f32 %0, %1;" : "=r"(u) : "f"(f)); return u;
}

__device__ __forceinline__ void mma8(float* c, const uint32_t* a,
                                     uint32_t b0, uint32_t b1) {
    asm volatile(
        "mma.sync.aligned.m16n8k8.row.col.f32.tf32.tf32.f32 "
        "{%0,%1,%2,%3}, {%4,%5,%6,%7}, {%8,%9}, {%0,%1,%2,%3};"
        : "+f"(c[0]), "+f"(c[1]), "+f"(c[2]), "+f"(c[3])
        : "r"(a[0]), "r"(a[1]), "r"(a[2]), "r"(a[3]), "r"(b0), "r"(b1));
}

// ---------------- weight pre-transform: W[E][OUT][IN] -> fragment order ----------------
template <int IN, int OUT>
__global__ void prep(const float* __restrict__ W, float* __restrict__ WF) {
    int idx = blockIdx.x * blockDim.x + threadIdx.x;   // one uint4 per thread
    constexpr int NTPC = OUT / 16;
    constexpr int GS   = IN / 8;
    if (idx >= NE * GS * NTPC * 32) return;
    int lane = idx & 31;
    int rest = idx >> 5;
    int ntp  = rest % NTPC;
    int gs   = (rest / NTPC) % GS;
    int e    = rest / (NTPC * GS);
    int n0 = ntp * 16 + (lane >> 2);
    int k0 = gs * 8 + (lane & 3);
    const float* We = W + (size_t)e * OUT * IN;
    uint4 v;
    v.x = f2tf(We[(size_t)(n0 + 0) * IN + k0]);
    v.y = f2tf(We[(size_t)(n0 + 0) * IN + k0 + 4]);
    v.z = f2tf(We[(size_t)(n0 + 8) * IN + k0]);
    v.w = f2tf(We[(size_t)(n0 + 8) * IN + k0 + 4]);
    ((uint4*)WF)[idx] = v;
}

// ---------------- mask dtype detection + counter zeroing ----------------
__global__ void detect_and_zero(const unsigned char* __restrict__ m) {
    __shared__ int bad;
    if (threadIdx.x == 0) bad = 0;
    if (threadIdx.x < 48) ((int*)g_cnt)[threadIdx.x] = 0;
    __syncthreads();
    int t = threadIdx.x;
    #pragma unroll
    for (int k = 0; k < NK; k++) {
        int s = 0;
        #pragma unroll
        for (int e = 0; e < NE; e++)
            s += (m[(e * NK + k) * T_TOK + t] != 0) ? 1 : 0;
        if (s != 1) bad = 1;
    }
    __syncthreads();
    if (threadIdx.x == 0) g_maskmode = bad ? 0 : 1;
}

// ---------------- routing ----------------
__global__ void route3(const unsigned char* __restrict__ m1,
                       const unsigned char* __restrict__ m2,
                       const unsigned char* __restrict__ m3,
                       const float* __restrict__ r1,
                       const float* __restrict__ r2,
                       const float* __restrict__ r3) {
    int tid = blockIdx.x * blockDim.x + threadIdx.x;
    if (tid >= 3 * NK * T_TOK) return;
    int s   = tid / (NK * T_TOK);
    int rem = tid % (NK * T_TOK);
    int k   = rem / T_TOK;
    int t   = rem % T_TOK;
    const unsigned char* m = (s == 0) ? m1 : (s == 1) ? m2 : m3;
    const float*         r = (s == 0) ? r1 : (s == 1) ? r2 : r3;

    int e = 0;
    if (g_maskmode) {
        #pragma unroll
        for (int i = 0; i < NE; i++)
            if (m[(i * NK + k) * T_TOK + t]) e = i;
    } else {
        const int* mi = (const int*)m;
        #pragma unroll
        for (int i = 0; i < NE; i++)
            if (mi[(i * NK + k) * T_TOK + t]) e = i;
    }
    float w = r[t * NK + k];
    int g = k * NE + e;
    int p = atomicAdd(&g_cnt[s][g], 1);
    g_tok[s][g][p] = t;
    g_wgt[s][g][p] = w;
}

// ---------------- tf32 mma.sync gathered expert GEMM ----------------
// BM=128, BN=128, BK=16, 128 threads, 4 warps (2m x 2n), warp tile 64x64.
// A: gather -> tf32 -> smem [step][mtile][reg][lane] via sts.128; consumer lds.32 x4.
// B: prep'd fragment gmem -> raw coalesced smem copy; consumer lds.128.
template <int STAGE, int IN, int OUT, bool RELU>
__global__ __launch_bounds__(128, 2)
void moe_mma(const float* __restrict__ X,
             const float* __restrict__ Bias) {
    const float *A0, *A1, *WFg;
    float *O0, *O1;
    if constexpr (STAGE == 0)      { A0 = X;     A1 = nullptr; O0 = g_h1a; O1 = g_h1b; WFg = g_wf1; }
    else if constexpr (STAGE == 1) { A0 = g_h1a; A1 = g_h1b;   O0 = g_h2a; O1 = g_h2b; WFg = g_wf2; }
    else                           { A0 = g_h2a; A1 = g_h2b;   O0 = g_h3a; O1 = g_h3b; WFg = g_wf3; }
    constexpr bool SUMIN = (STAGE != 0);
    constexpr int  NTPC  = OUT / 16;

    const int g  = blockIdx.z;                 // slot*8 + expert
    const int n  = g_cnt[STAGE][g];
    const int m0 = blockIdx.x * 128;
    if (m0 >= n) return;
    const int e  = g & 7;
    const int n0 = blockIdx.y * 128;
    float* Out = (g >= 8) ? O1 : O0;

    // A: [buf][step2][mtile8][reg4][lane32] floats ; B: [buf][step2][ntp8][lane32] uint4
    __shared__ float sA[2][2 * 8 * 4 * 32];
    __shared__ uint4 sB[2][2 * 8 * 32];
    __shared__ int   s_tok[128];
    __shared__ float s_w[128];

    const int tid  = threadIdx.x;
    const int wid  = tid >> 5;
    const int lane = tid & 31;
    const int wm   = wid >> 1;   // 0..1
    const int wn   = wid & 1;    // 0..1

    {
        int gi  = m0 + tid;
        int src = (gi < n) ? gi : (n - 1);
        s_tok[tid] = g_tok[STAGE][g][src];
        s_w[tid]   = (gi < n) ? g_wgt[STAGE][g][src] : 0.0f;
    }
    __syncthreads();

    const uint4* WFe = (const uint4*)(WFg + (size_t)e * (IN / 8) * NTPC * 128);
    const int ntp0 = blockIdx.y * 8;
    const int myrow = s_tok[tid];

    float c[4][8][4];
    #pragma unroll
    for (int a = 0; a < 4; a++)
        #pragma unroll
        for (int b = 0; b < 8; b++)
            #pragma unroll
            for (int d = 0; d < 4; d++) c[a][b][d] = 0.0f;

    float4 va[4];
    uint4  vb[4];

    // thread t owns gathered row t, full BK=16 k-slice
    auto LOADA = [&](int kb) {
        #pragma unroll
        for (int j = 0; j < 4; j++) {
            float4 v = *(const float4*)(A0 + (size_t)myrow * IN + kb + j * 4);
            if constexpr (SUMIN) {
                float4 v2 = *(const float4*)(A1 + (size_t)myrow * IN + kb + j * 4);
                v.x += v2.x; v.y += v2.y; v.z += v2.z; v.w += v2.w;
            }
            va[j] = v;
        }
    };

    auto LOADB = [&](int ch) {
        #pragma unroll
        for (int s = 0; s < 2; s++) {
            const uint4* p = WFe + ((size_t)(ch * 2 + s) * NTPC + ntp0) * 32;
            vb[s * 2 + 0] = p[tid];
            vb[s * 2 + 1] = p[tid + 128];
        }
    };

    auto STS = [&](int buf) {
        const int rb3   = (tid >> 3) & 1;
        const int mt    = tid >> 4;
        const int lane0 = (tid & 7) * 4;
        #pragma unroll
        for (int j = 0; j < 4; j++) {
            int step = j >> 1, h = j & 1;
            int reg = 2 * h + rb3;
            uint4 u = { f2tf(va[j].x), f2tf(va[j].y), f2tf(va[j].z), f2tf(va[j].w) };
            *(uint4*)&sA[buf][(((step * 8 + mt) * 4 + reg) * 32) + lane0] = u;
        }
        #pragma unroll
        for (int s = 0; s < 2; s++) {
            sB[buf][s * 256 + tid]       = vb[s * 2 + 0];
            sB[buf][s * 256 + tid + 128] = vb[s * 2 + 1];
        }
    };

    auto COMP = [&](int buf) {
        #pragma unroll
        for (int s = 0; s < 2; s++) {
            uint32_t a[4][4];
            #pragma unroll
            for (int mi = 0; mi < 4; mi++) {
                const float* base = &sA[buf][((s * 8 + wm * 4 + mi) * 4) * 32 + lane];
                #pragma unroll
                for (int r = 0; r < 4; r++)
                    a[mi][r] = __float_as_uint(base[r * 32]);
            }
            uint4 b[4];
            #pragma unroll
            for (int p = 0; p < 4; p++)
                b[p] = sB[buf][s * 256 + (wn * 4 + p) * 32 + lane];
            #pragma unroll
            for (int mi = 0; mi < 4; mi++)
                #pragma unroll
                for (int p = 0; p < 4; p++) {
                    mma8(c[mi][p * 2 + 0], a[mi], b[p].x, b[p].y);
                    mma8(c[mi][p * 2 + 1], a[mi], b[p].z, b[p].w);
                }
        }
    };

    constexpr int NC = IN / 16;
    LOADA(0);
    LOADB(0);
    STS(0);
    __syncthreads();
    for (int ch = 0; ch < NC; ch++) {
        if (ch + 1 < NC) {
            LOADA((ch + 1) * 16);
            LOADB(ch + 1);
        }
        COMP(ch & 1);
        if (ch + 1 < NC) {
            STS((ch + 1) & 1);
            __syncthreads();
        }
    }

    // --- epilogue: bias (+relu) * routing weight, scatter by token ---
    float2 bias[8];
    #pragma unroll
    for (int nt = 0; nt < 8; nt++) {
        int col = wn * 64 + (nt >> 1) * 16 + (nt & 1) * 8 + (lane & 3) * 2;
        bias[nt] = *(const float2*)&Bias[e * OUT + n0 + col];
    }

    #pragma unroll
    for (int mi = 0; mi < 4; mi++) {
        #pragma unroll
        for (int half = 0; half < 2; half++) {
            int r  = wm * 64 + mi * 16 + (lane >> 2) + half * 8;
            int gi = m0 + r;
            if (gi >= n) continue;
            int   t = s_tok[r];
            float w = s_w[r];
            #pragma unroll
            for (int nt = 0; nt < 8; nt++) {
                int col = wn * 64 + (nt >> 1) * 16 + (nt & 1) * 8 + (lane & 3) * 2;
                float2 v;
                v.x = c[mi][nt][half * 2 + 0] + bias[nt].x;
                v.y = c[mi][nt][half * 2 + 1] + bias[nt].y;
                if constexpr (RELU) {
                    v.x = fmaxf(v.x, 0.0f);
                    v.y = fmaxf(v.y, 0.0f);
                }
                v.x *= w; v.y *= w;
                *(float2*)&Out[(size_t)t * OUT + n0 + col] = v;
            }
        }
    }
}

// ---------------- final combine + relu ----------------
__global__ void finalize(float* __restrict__ out) {
    int i = blockIdx.x * blockDim.x + threadIdx.x;
    float4 a = ((const float4*)g_h3a)[i];
    float4 b = ((const float4*)g_h3b)[i];
    float4 v;
    v.x = fmaxf(a.x + b.x, 0.0f);
    v.y = fmaxf(a.y + b.y, 0.0f);
    v.z = fmaxf(a.z + b.z, 0.0f);
    v.w = fmaxf(a.w + b.w, 0.0f);
    ((float4*)out)[i] = v;
}

// ---------------- launch ----------------
extern "C" void kernel_launch(void* const* d_in, const int* in_sizes, int n_in,
                              void* d_out, int out_size) {
    const float*         x  = (const float*)d_in[0];
    const unsigned char* m1 = (const unsigned char*)d_in[1];
    const unsigned char* m2 = (const unsigned char*)d_in[2];
    const unsigned char* m3 = (const unsigned char*)d_in[3];
    const float*         r1 = (const float*)d_in[4];
    const float*         r2 = (const float*)d_in[5];
    const float*         r3 = (const float*)d_in[6];
    const float*         W1 = (const float*)d_in[7];
    const float*         b1 = (const float*)d_in[8];
    const float*         W2 = (const float*)d_in[9];
    const float*         b2 = (const float*)d_in[10];
    const float*         W3 = (const float*)d_in[11];
    const float*         b3 = (const float*)d_in[12];
    float* out = (float*)d_out;

    float *wf1, *wf2, *wf3;
    cudaGetSymbolAddress((void**)&wf1, g_wf1);
    cudaGetSymbolAddress((void**)&wf2, g_wf2);
    cudaGetSymbolAddress((void**)&wf3, g_wf3);

    detect_and_zero<<<1, 256>>>(m1);
    route3<<<(3 * NK * T_TOK + 255) / 256, 256>>>(m1, m2, m3, r1, r2, r3);

    prep<512, 256><<<(NE * 64 * 16 * 32 + 255) / 256, 256>>>(W1, wf1);
    prep<256, 256><<<(NE * 32 * 16 * 32 + 255) / 256, 256>>>(W2, wf2);
    prep<256, 512><<<(NE * 32 * 32 * 32 + 255) / 256, 256>>>(W3, wf3);

    dim3 g1(T_TOK / 128, 256 / 128, 16);
    dim3 g2(T_TOK / 128, 256 / 128, 16);
    dim3 g3(T_TOK / 128, 512 / 128, 16);
    moe_mma<0, 512, 256, false><<<g1, 128>>>(x, b1);
    moe_mma<1, 256, 256, false><<<g2, 128>>>(nullptr, b2);
    moe_mma<2, 256, 512, true ><<<g3, 128>>>(nullptr, b3);

    finalize<<<(T_TOK * 512 / 4) / 256, 256>>>(out);
}

// round 6
// speedup vs baseline: 1.1886x; 1.1397x over previous
#include <cuda_runtime.h>
#include <cstdint>

#define T_TOK 16384
#define NE 8
#define NK 2

// ---------------- scratch (device globals; no allocation allowed) ----------------
__device__ int   g_maskmode;
__device__ int   g_cnt[3][16];
__device__ int   g_tok[3][16][T_TOK];
__device__ float g_wgt[3][16][T_TOK];
__device__ float g_h1a[T_TOK * 256];
__device__ float g_h1b[T_TOK * 256];
__device__ float g_h2a[T_TOK * 256];
__device__ float g_h2b[T_TOK * 256];
__device__ float g_h3a[T_TOK * 512];
__device__ float g_h3b[T_TOK * 512];
// fragment-ordered tf32 weights: [e][gs(IN/8)][ntp(OUT/16)][lane32][4]
__device__ float g_wf1[NE * 64 * 16 * 128];   // stage0: IN=512, OUT=256
__device__ float g_wf2[NE * 32 * 16 * 128];   // stage1: IN=256, OUT=256
__device__ float g_wf3[NE * 32 * 32 * 128];   // stage2: IN=256, OUT=512

// ---------------- helpers ----------------
__device__ __forceinline__ uint32_t f2tf(float f) {
    uint32_t u; asm("cvt.rn.tf32.f32 %0, %1;" : "=r"(u) : "f"(f)); return u;
}

__device__ __forceinline__ void mma8(float* c, const uint32_t* a,
                                     uint32_t b0, uint32_t b1) {
    asm volatile(
        "mma.sync.aligned.m16n8k8.row.col.f32.tf32.tf32.f32 "
        "{%0,%1,%2,%3}, {%4,%5,%6,%7}, {%8,%9}, {%0,%1,%2,%3};"
        : "+f"(c[0]), "+f"(c[1]), "+f"(c[2]), "+f"(c[3])
        : "r"(a[0]), "r"(a[1]), "r"(a[2]), "r"(a[3]), "r"(b0), "r"(b1));
}

__device__ __forceinline__ void cp16(uint32_t smem_dst, const void* gsrc) {
    asm volatile("cp.async.cg.shared.global [%0], [%1], 16;"
                 :: "r"(smem_dst), "l"(gsrc));
}

// ---------------- single merged weight pre-transform ----------------
template <int IN, int OUT>
__device__ __forceinline__ void prep_one(int idx, const float* W, float* WF) {
    constexpr int NTPC = OUT / 16;
    constexpr int GS   = IN / 8;
    int lane = idx & 31;
    int rest = idx >> 5;
    int ntp  = rest % NTPC;
    int gs   = (rest / NTPC) % GS;
    int e    = rest / (NTPC * GS);
    int n0 = ntp * 16 + (lane >> 2);
    int k0 = gs * 8 + (lane & 3);
    const float* We = W + (size_t)e * OUT * IN;
    uint4 v;
    v.x = f2tf(We[(size_t)(n0 + 0) * IN + k0]);
    v.y = f2tf(We[(size_t)(n0 + 0) * IN + k0 + 4]);
    v.z = f2tf(We[(size_t)(n0 + 8) * IN + k0]);
    v.w = f2tf(We[(size_t)(n0 + 8) * IN + k0 + 4]);
    ((uint4*)WF)[idx] = v;
}

__global__ void prep_all(const float* __restrict__ W1,
                         const float* __restrict__ W2,
                         const float* __restrict__ W3,
                         float* __restrict__ WF1,
                         float* __restrict__ WF2,
                         float* __restrict__ WF3) {
    constexpr int N1 = NE * 64 * 16 * 32;    // 262144
    constexpr int N2 = NE * 32 * 16 * 32;    // 131072
    constexpr int N3 = NE * 32 * 32 * 32;    // 262144
    int idx = blockIdx.x * blockDim.x + threadIdx.x;
    if (idx < N1) { prep_one<512, 256>(idx, W1, WF1); return; }
    idx -= N1;
    if (idx < N2) { prep_one<256, 256>(idx, W2, WF2); return; }
    idx -= N2;
    if (idx < N3) { prep_one<256, 512>(idx, W3, WF3); }
}

// ---------------- mask dtype detection + counter zeroing ----------------
__global__ void detect_and_zero(const unsigned char* __restrict__ m) {
    __shared__ int bad;
    if (threadIdx.x == 0) bad = 0;
    if (threadIdx.x < 48) ((int*)g_cnt)[threadIdx.x] = 0;
    __syncthreads();
    int t = threadIdx.x;
    #pragma unroll
    for (int k = 0; k < NK; k++) {
        int s = 0;
        #pragma unroll
        for (int e = 0; e < NE; e++)
            s += (m[(e * NK + k) * T_TOK + t] != 0) ? 1 : 0;
        if (s != 1) bad = 1;
    }
    __syncthreads();
    if (threadIdx.x == 0) g_maskmode = bad ? 0 : 1;
}

// ---------------- routing ----------------
__global__ void route3(const unsigned char* __restrict__ m1,
                       const unsigned char* __restrict__ m2,
                       const unsigned char* __restrict__ m3,
                       const float* __restrict__ r1,
                       const float* __restrict__ r2,
                       const float* __restrict__ r3) {
    int tid = blockIdx.x * blockDim.x + threadIdx.x;
    if (tid >= 3 * NK * T_TOK) return;
    int s   = tid / (NK * T_TOK);
    int rem = tid % (NK * T_TOK);
    int k   = rem / T_TOK;
    int t   = rem % T_TOK;
    const unsigned char* m = (s == 0) ? m1 : (s == 1) ? m2 : m3;
    const float*         r = (s == 0) ? r1 : (s == 1) ? r2 : r3;

    int e = 0;
    if (g_maskmode) {
        #pragma unroll
        for (int i = 0; i < NE; i++)
            if (m[(i * NK + k) * T_TOK + t]) e = i;
    } else {
        const int* mi = (const int*)m;
        #pragma unroll
        for (int i = 0; i < NE; i++)
            if (mi[(i * NK + k) * T_TOK + t]) e = i;
    }
    float w = r[t * NK + k];
    int g = k * NE + e;
    int p = atomicAdd(&g_cnt[s][g], 1);
    g_tok[s][g][p] = t;
    g_wgt[s][g][p] = w;
}

// ---------------- tf32 mma.sync gathered expert GEMM ----------------
// BM=128, BN=128, BK=16, 256 threads, 8 warps (2m x 4n), warp tile 64x32.
// A: gather -> tf32 -> smem [step][mt][reg][lane] via 2x sts.128/thread.
// B: cp.async 16B/thread straight from prep'd fragment gmem (no registers).
template <int STAGE, int IN, int OUT, bool RELU>
__global__ __launch_bounds__(256, 2)
void moe_mma(const float* __restrict__ X,
             const float* __restrict__ Bias) {
    const float *A0, *A1, *WFg;
    float *O0, *O1;
    if constexpr (STAGE == 0)      { A0 = X;     A1 = nullptr; O0 = g_h1a; O1 = g_h1b; WFg = g_wf1; }
    else if constexpr (STAGE == 1) { A0 = g_h1a; A1 = g_h1b;   O0 = g_h2a; O1 = g_h2b; WFg = g_wf2; }
    else                           { A0 = g_h2a; A1 = g_h2b;   O0 = g_h3a; O1 = g_h3b; WFg = g_wf3; }
    constexpr bool SUMIN = (STAGE != 0);
    constexpr int  NTPC  = OUT / 16;

    const int g  = blockIdx.z;                 // slot*8 + expert
    const int n  = g_cnt[STAGE][g];
    const int m0 = blockIdx.x * 128;
    if (m0 >= n) return;
    const int e  = g & 7;
    const int n0 = blockIdx.y * 128;
    float* Out = (g >= 8) ? O1 : O0;

    // A: [buf][step2][mt8][reg4][lane32] floats ; B: [buf][step2][ntp8][lane32] uint4
    __shared__ float sA[2][2 * 8 * 4 * 32];
    __shared__ uint4 sB[2][2 * 8 * 32];
    __shared__ int   s_tok[128];
    __shared__ float s_w[128];

    const int tid  = threadIdx.x;
    const int wid  = tid >> 5;
    const int lane = tid & 31;
    const int wm   = wid >> 2;   // 0..1
    const int wn   = wid & 3;    // 0..3

    if (tid < 128) {
        int gi  = m0 + tid;
        int src = (gi < n) ? gi : (n - 1);
        s_tok[tid] = g_tok[STAGE][g][src];
        s_w[tid]   = (gi < n) ? g_wgt[STAGE][g][src] : 0.0f;
    }
    __syncthreads();

    const uint4* WFe = (const uint4*)(WFg + (size_t)e * (IN / 8) * NTPC * 128);
    const int ntp0 = blockIdx.y * 8;

    // A producer: thread owns half-row: row = tid>>1, k-half (step) = tid&1
    const int arow  = tid >> 1;
    const int astep = tid & 1;
    const int atok  = s_tok[arow];
    const int amt   = arow >> 4;
    const int arb3  = (arow >> 3) & 1;
    const int alane0 = (arow & 7) * 4;
    // B producer: 2 cp.async per thread over [s2][p8][lane32] = 512 frags
    const int bs0 = tid >> 8, bp0 = (tid >> 5) & 7, bl0 = tid & 31;          // tid
    const int ti2 = tid + 256;
    const int bs1 = ti2 >> 8, bp1 = (ti2 >> 5) & 7, bl1 = ti2 & 31;

    float c[4][4][4];
    #pragma unroll
    for (int a = 0; a < 4; a++)
        #pragma unroll
        for (int b = 0; b < 4; b++)
            #pragma unroll
            for (int d = 0; d < 4; d++) c[a][b][d] = 0.0f;

    float4 va[2];

    auto LOADA = [&](int kb) {
        #pragma unroll
        for (int h = 0; h < 2; h++) {
            int koff = kb + astep * 8 + h * 4;
            float4 v = *(const float4*)(A0 + (size_t)atok * IN + koff);
            if constexpr (SUMIN) {
                float4 v2 = *(const float4*)(A1 + (size_t)atok * IN + koff);
                v.x += v2.x; v.y += v2.y; v.z += v2.z; v.w += v2.w;
            }
            va[h] = v;
        }
    };

    auto STSA = [&](int buf) {
        #pragma unroll
        for (int h = 0; h < 2; h++) {
            int reg = 2 * h + arb3;
            uint4 u = { f2tf(va[h].x), f2tf(va[h].y), f2tf(va[h].z), f2tf(va[h].w) };
            *(uint4*)&sA[buf][(((astep * 8 + amt) * 4 + reg) * 32) + alane0] = u;
        }
    };

    auto CPB = [&](int ch, int buf) {
        uint32_t dst = (uint32_t)__cvta_generic_to_shared(&sB[buf][0]);
        cp16(dst + tid * 16,
             WFe + ((size_t)(ch * 2 + bs0) * NTPC + ntp0 + bp0) * 32 + bl0);
        cp16(dst + ti2 * 16,
             WFe + ((size_t)(ch * 2 + bs1) * NTPC + ntp0 + bp1) * 32 + bl1);
        asm volatile("cp.async.commit_group;" ::: "memory");
    };

    auto COMP = [&](int buf) {
        #pragma unroll
        for (int s = 0; s < 2; s++) {
            uint32_t a[4][4];
            #pragma unroll
            for (int mi = 0; mi < 4; mi++) {
                const float* base = &sA[buf][((s * 8 + wm * 4 + mi) * 4) * 32 + lane];
                #pragma unroll
                for (int r = 0; r < 4; r++)
                    a[mi][r] = __float_as_uint(base[r * 32]);
            }
            uint4 b[2];
            b[0] = sB[buf][s * 256 + (wn * 2 + 0) * 32 + lane];
            b[1] = sB[buf][s * 256 + (wn * 2 + 1) * 32 + lane];
            #pragma unroll
            for (int mi = 0; mi < 4; mi++) {
                mma8(c[mi][0], a[mi], b[0].x, b[0].y);
                mma8(c[mi][1], a[mi], b[0].z, b[0].w);
                mma8(c[mi][2], a[mi], b[1].x, b[1].y);
                mma8(c[mi][3], a[mi], b[1].z, b[1].w);
            }
        }
    };

    constexpr int NC = IN / 16;
    CPB(0, 0);
    LOADA(0);
    STSA(0);
    asm volatile("cp.async.wait_group 0;" ::: "memory");
    __syncthreads();
    for (int ch = 0; ch < NC; ch++) {
        if (ch + 1 < NC) {
            LOADA((ch + 1) * 16);
            CPB(ch + 1, (ch + 1) & 1);
        }
        COMP(ch & 1);
        if (ch + 1 < NC) {
            STSA((ch + 1) & 1);
            asm volatile("cp.async.wait_group 0;" ::: "memory");
            __syncthreads();
        }
    }

    // --- epilogue: bias (+relu) * routing weight, scatter by token ---
    float2 bias[4];
    #pragma unroll
    for (int nt = 0; nt < 4; nt++)
        bias[nt] = *(const float2*)&Bias[e * OUT + n0 + wn * 32 + nt * 8 + (lane & 3) * 2];

    #pragma unroll
    for (int mi = 0; mi < 4; mi++) {
        #pragma unroll
        for (int half = 0; half < 2; half++) {
            int r  = wm * 64 + mi * 16 + (lane >> 2) + half * 8;
            int gi = m0 + r;
            if (gi >= n) continue;
            int   t = s_tok[r];
            float w = s_w[r];
            #pragma unroll
            for (int nt = 0; nt < 4; nt++) {
                float2 v;
                v.x = c[mi][nt][half * 2 + 0] + bias[nt].x;
                v.y = c[mi][nt][half * 2 + 1] + bias[nt].y;
                if constexpr (RELU) {
                    v.x = fmaxf(v.x, 0.0f);
                    v.y = fmaxf(v.y, 0.0f);
                }
                v.x *= w; v.y *= w;
                *(float2*)&Out[(size_t)t * OUT + n0 + wn * 32 + nt * 8 + (lane & 3) * 2] = v;
            }
        }
    }
}

// ---------------- final combine + relu ----------------
__global__ void finalize(float* __restrict__ out) {
    int i = blockIdx.x * blockDim.x + threadIdx.x;
    float4 a = ((const float4*)g_h3a)[i];
    float4 b = ((const float4*)g_h3b)[i];
    float4 v;
    v.x = fmaxf(a.x + b.x, 0.0f);
    v.y = fmaxf(a.y + b.y, 0.0f);
    v.z = fmaxf(a.z + b.z, 0.0f);
    v.w = fmaxf(a.w + b.w, 0.0f);
    ((float4*)out)[i] = v;
}

// ---------------- launch ----------------
extern "C" void kernel_launch(void* const* d_in, const int* in_sizes, int n_in,
                              void* d_out, int out_size) {
    const float*         x  = (const float*)d_in[0];
    const unsigned char* m1 = (const unsigned char*)d_in[1];
    const unsigned char* m2 = (const unsigned char*)d_in[2];
    const unsigned char* m3 = (const unsigned char*)d_in[3];
    const float*         r1 = (const float*)d_in[4];
    const float*         r2 = (const float*)d_in[5];
    const float*         r3 = (const float*)d_in[6];
    const float*         W1 = (const float*)d_in[7];
    const float*         b1 = (const float*)d_in[8];
    const float*         W2 = (const float*)d_in[9];
    const float*         b2 = (const float*)d_in[10];
    const float*         W3 = (const float*)d_in[11];
    const float*         b3 = (const float*)d_in[12];
    float* out = (float*)d_out;

    float *wf1, *wf2, *wf3;
    cudaGetSymbolAddress((void**)&wf1, g_wf1);
    cudaGetSymbolAddress((void**)&wf2, g_wf2);
    cudaGetSymbolAddress((void**)&wf3, g_wf3);

    detect_and_zero<<<1, 256>>>(m1);
    route3<<<(3 * NK * T_TOK + 255) / 256, 256>>>(m1, m2, m3, r1, r2, r3);

    constexpr int PREP_N = NE * 64 * 16 * 32 + NE * 32 * 16 * 32 + NE * 32 * 32 * 32;
    prep_all<<<(PREP_N + 255) / 256, 256>>>(W1, W2, W3, wf1, wf2, wf3);

    dim3 g1(T_TOK / 128, 256 / 128, 16);
    dim3 g2(T_TOK / 128, 256 / 128, 16);
    dim3 g3(T_TOK / 128, 512 / 128, 16);
    moe_mma<0, 512, 256, false><<<g1, 256>>>(x, b1);
    moe_mma<1, 256, 256, false><<<g2, 256>>>(nullptr, b2);
    moe_mma<2, 256, 512, true ><<<g3, 256>>>(nullptr, b3);

    finalize<<<(T_TOK * 512 / 4) / 256, 256>>>(out);
}

// round 7
// speedup vs baseline: 1.2483x; 1.0502x over previous
#include <cuda_runtime.h>
#include <cstdint>

#define T_TOK 16384
#define NE 8
#define NK 2

// ---------------- scratch (device globals; no allocation allowed) ----------------
__device__ int   g_maskmode;
__device__ int   g_cnt[3][16];
__device__ int   g_tok[3][16][T_TOK];
__device__ float g_wgt[3][16][T_TOK];
__device__ float g_h1a[T_TOK * 256];
__device__ float g_h1b[T_TOK * 256];
__device__ float g_h2a[T_TOK * 256];
__device__ float g_h2b[T_TOK * 256];
__device__ float g_h3a[T_TOK * 512];
__device__ float g_h3b[T_TOK * 512];
// fragment-ordered tf32 weights: [e][gs(IN/8)][ntp(OUT/16)][lane32][4]
__device__ float g_wf1[NE * 64 * 16 * 128];   // stage0: IN=512, OUT=256
__device__ float g_wf2[NE * 32 * 16 * 128];   // stage1: IN=256, OUT=256
__device__ float g_wf3[NE * 32 * 32 * 128];   // stage2: IN=256, OUT=512

// ---------------- helpers ----------------
__device__ __forceinline__ uint32_t f2tf(float f) {
    uint32_t u; asm("cvt.rn.tf32.f32 %0, %1;" : "=r"(u) : "f"(f)); return u;
}

__device__ __forceinline__ void mma8(float* c, const uint32_t* a,
                                     uint32_t b0, uint32_t b1) {
    asm volatile(
        "mma.sync.aligned.m16n8k8.row.col.f32.tf32.tf32.f32 "
        "{%0,%1,%2,%3}, {%4,%5,%6,%7}, {%8,%9}, {%0,%1,%2,%3};"
        : "+f"(c[0]), "+f"(c[1]), "+f"(c[2]), "+f"(c[3])
        : "r"(a[0]), "r"(a[1]), "r"(a[2]), "r"(a[3]), "r"(b0), "r"(b1));
}

__device__ __forceinline__ void cp16(uint32_t smem_dst, const void* gsrc) {
    asm volatile("cp.async.cg.shared.global [%0], [%1], 16;"
                 :: "r"(smem_dst), "l"(gsrc));
}

// ---------------- single merged weight pre-transform ----------------
template <int IN, int OUT>
__device__ __forceinline__ void prep_one(int idx, const float* W, float* WF) {
    constexpr int NTPC = OUT / 16;
    constexpr int GS   = IN / 8;
    int lane = idx & 31;
    int rest = idx >> 5;
    int ntp  = rest % NTPC;
    int gs   = (rest / NTPC) % GS;
    int e    = rest / (NTPC * GS);
    int n0 = ntp * 16 + (lane >> 2);
    int k0 = gs * 8 + (lane & 3);
    const float* We = W + (size_t)e * OUT * IN;
    uint4 v;
    v.x = f2tf(We[(size_t)(n0 + 0) * IN + k0]);
    v.y = f2tf(We[(size_t)(n0 + 0) * IN + k0 + 4]);
    v.z = f2tf(We[(size_t)(n0 + 8) * IN + k0]);
    v.w = f2tf(We[(size_t)(n0 + 8) * IN + k0 + 4]);
    ((uint4*)WF)[idx] = v;
}

__global__ void prep_all(const float* __restrict__ W1,
                         const float* __restrict__ W2,
                         const float* __restrict__ W3,
                         float* __restrict__ WF1,
                         float* __restrict__ WF2,
                         float* __restrict__ WF3) {
    constexpr int N1 = NE * 64 * 16 * 32;
    constexpr int N2 = NE * 32 * 16 * 32;
    constexpr int N3 = NE * 32 * 32 * 32;
    int idx = blockIdx.x * blockDim.x + threadIdx.x;
    if (idx < N1) { prep_one<512, 256>(idx, W1, WF1); return; }
    idx -= N1;
    if (idx < N2) { prep_one<256, 256>(idx, W2, WF2); return; }
    idx -= N2;
    if (idx < N3) { prep_one<256, 512>(idx, W3, WF3); }
}

// ---------------- mask dtype detection + counter zeroing ----------------
__global__ void detect_and_zero(const unsigned char* __restrict__ m) {
    __shared__ int bad;
    if (threadIdx.x == 0) bad = 0;
    if (threadIdx.x < 48) ((int*)g_cnt)[threadIdx.x] = 0;
    __syncthreads();
    int t = threadIdx.x;
    #pragma unroll
    for (int k = 0; k < NK; k++) {
        int s = 0;
        #pragma unroll
        for (int e = 0; e < NE; e++)
            s += (m[(e * NK + k) * T_TOK + t] != 0) ? 1 : 0;
        if (s != 1) bad = 1;
    }
    __syncthreads();
    if (threadIdx.x == 0) g_maskmode = bad ? 0 : 1;
}

// ---------------- routing ----------------
__global__ void route3(const unsigned char* __restrict__ m1,
                       const unsigned char* __restrict__ m2,
                       const unsigned char* __restrict__ m3,
                       const float* __restrict__ r1,
                       const float* __restrict__ r2,
                       const float* __restrict__ r3) {
    int tid = blockIdx.x * blockDim.x + threadIdx.x;
    if (tid >= 3 * NK * T_TOK) return;
    int s   = tid / (NK * T_TOK);
    int rem = tid % (NK * T_TOK);
    int k   = rem / T_TOK;
    int t   = rem % T_TOK;
    const unsigned char* m = (s == 0) ? m1 : (s == 1) ? m2 : m3;
    const float*         r = (s == 0) ? r1 : (s == 1) ? r2 : r3;

    int e = 0;
    if (g_maskmode) {
        #pragma unroll
        for (int i = 0; i < NE; i++)
            if (m[(i * NK + k) * T_TOK + t]) e = i;
    } else {
        const int* mi = (const int*)m;
        #pragma unroll
        for (int i = 0; i < NE; i++)
            if (mi[(i * NK + k) * T_TOK + t]) e = i;
    }
    float w = r[t * NK + k];
    int g = k * NE + e;
    int p = atomicAdd(&g_cnt[s][g], 1);
    g_tok[s][g][p] = t;
    g_wgt[s][g][p] = w;
}

// ---------------- tf32 mma.sync gathered expert GEMM ----------------
// BM=128, BN=128, BK=32 (4 k8 steps), 256 threads, 8 warps (2m x 4n), warp 64x32.
// A: gather -> tf32 -> smem [step][mt][reg][lane], 4x sts.128/thread.
// B: 4x cp.async.cg/thread from prep'd fragment gmem. Double-buffered, 1 sync/chunk.
// Dynamic smem layout (bytes):
//   sA: 2 x 16384 @ 0      sB: 2 x 16384 @ 32768
//   s_tok: 512 @ 65536     s_w: 512 @ 66048        total 66560
#define SMEM_TOTAL_BYTES 66560

template <int STAGE, int IN, int OUT, bool RELU>
__global__ __launch_bounds__(256, 2)
void moe_mma(const float* __restrict__ X,
             const float* __restrict__ Bias) {
    const float *A0, *A1, *WFg;
    float *O0, *O1;
    if constexpr (STAGE == 0)      { A0 = X;     A1 = nullptr; O0 = g_h1a; O1 = g_h1b; WFg = g_wf1; }
    else if constexpr (STAGE == 1) { A0 = g_h1a; A1 = g_h1b;   O0 = g_h2a; O1 = g_h2b; WFg = g_wf2; }
    else                           { A0 = g_h2a; A1 = g_h2b;   O0 = g_h3a; O1 = g_h3b; WFg = g_wf3; }
    constexpr bool SUMIN = (STAGE != 0);
    constexpr int  NTPC  = OUT / 16;

    const int g  = blockIdx.z;                 // slot*8 + expert
    const int n  = g_cnt[STAGE][g];
    const int m0 = blockIdx.x * 128;
    if (m0 >= n) return;
    const int e  = g & 7;
    const int n0 = blockIdx.y * 128;
    float* Out = (g >= 8) ? O1 : O0;

    extern __shared__ __align__(16) char dsm[];
    float* sA    = (float*)dsm;                        // [buf][step4][mt8][reg4][lane32]
    uint4* sB    = (uint4*)(dsm + 32768);              // [buf][step4][ntp8][lane32]
    int*   s_tok = (int*)(dsm + 65536);
    float* s_w   = (float*)(dsm + 66048);

    const int tid  = threadIdx.x;
    const int wid  = tid >> 5;
    const int lane = tid & 31;
    const int wm   = wid >> 2;   // 0..1
    const int wn   = wid & 3;    // 0..3

    if (tid < 128) {
        int gi  = m0 + tid;
        int src = (gi < n) ? gi : (n - 1);
        s_tok[tid] = g_tok[STAGE][g][src];
        s_w[tid]   = (gi < n) ? g_wgt[STAGE][g][src] : 0.0f;
    }
    __syncthreads();

    const uint4* WFe = (const uint4*)(WFg + (size_t)e * (IN / 8) * NTPC * 128);
    const int ntp0 = blockIdx.y * 8;

    // A producer: thread owns half-row: row = tid>>1, k-half (16 vals) = tid&1
    const int arow   = tid >> 1;
    const int ahalf  = tid & 1;
    const int atok   = s_tok[arow];
    const int amt    = arow >> 4;
    const int arb3   = (arow >> 3) & 1;
    const int alane0 = (arow & 7) * 4;

    float c[4][4][4];
    #pragma unroll
    for (int a = 0; a < 4; a++)
        #pragma unroll
        for (int b = 0; b < 4; b++)
            #pragma unroll
            for (int d = 0; d < 4; d++) c[a][b][d] = 0.0f;

    float4 va[4];

    auto LOADA = [&](int kb) {
        #pragma unroll
        for (int j = 0; j < 4; j++) {
            int koff = kb + ahalf * 16 + j * 4;
            float4 v = *(const float4*)(A0 + (size_t)atok * IN + koff);
            if constexpr (SUMIN) {
                float4 v2 = *(const float4*)(A1 + (size_t)atok * IN + koff);
                v.x += v2.x; v.y += v2.y; v.z += v2.z; v.w += v2.w;
            }
            va[j] = v;
        }
    };

    auto STSA = [&](int buf) {
        float* base = sA + buf * 4096;
        #pragma unroll
        for (int j = 0; j < 4; j++) {
            int step = ahalf * 2 + (j >> 1);
            int reg  = 2 * (j & 1) + arb3;
            uint4 u = { f2tf(va[j].x), f2tf(va[j].y), f2tf(va[j].z), f2tf(va[j].w) };
            *(uint4*)&base[(((step * 8 + amt) * 4 + reg) * 32) + alane0] = u;
        }
    };

    auto CPB = [&](int ch, int buf) {
        uint32_t dst = (uint32_t)__cvta_generic_to_shared(sB + buf * 1024);
        #pragma unroll
        for (int i = 0; i < 4; i++) {
            int f  = tid + i * 256;                 // 0..1023 over [s4][p8][lane32]
            int bs = f >> 8;
            int bp = (f >> 5) & 7;
            int bl = f & 31;
            cp16(dst + f * 16,
                 WFe + ((size_t)(ch * 4 + bs) * NTPC + ntp0 + bp) * 32 + bl);
        }
        asm volatile("cp.async.commit_group;" ::: "memory");
    };

    auto COMP = [&](int buf) {
        const float* Ab = sA + buf * 4096;
        const uint4* Bb = sB + buf * 1024;
        #pragma unroll
        for (int s = 0; s < 4; s++) {
            uint32_t a[4][4];
            #pragma unroll
            for (int mi = 0; mi < 4; mi++) {
                const float* base = &Ab[((s * 8 + wm * 4 + mi) * 4) * 32 + lane];
                #pragma unroll
                for (int r = 0; r < 4; r++)
                    a[mi][r] = __float_as_uint(base[r * 32]);
            }
            uint4 b[2];
            b[0] = Bb[s * 256 + (wn * 2 + 0) * 32 + lane];
            b[1] = Bb[s * 256 + (wn * 2 + 1) * 32 + lane];
            #pragma unroll
            for (int mi = 0; mi < 4; mi++) {
                mma8(c[mi][0], a[mi], b[0].x, b[0].y);
                mma8(c[mi][1], a[mi], b[0].z, b[0].w);
                mma8(c[mi][2], a[mi], b[1].x, b[1].y);
                mma8(c[mi][3], a[mi], b[1].z, b[1].w);
            }
        }
    };

    constexpr int NC = IN / 32;
    CPB(0, 0);
    LOADA(0);
    STSA(0);
    asm volatile("cp.async.wait_group 0;" ::: "memory");
    __syncthreads();
    for (int ch = 0; ch < NC; ch++) {
        if (ch + 1 < NC) {
            LOADA((ch + 1) * 32);
            CPB(ch + 1, (ch + 1) & 1);
        }
        COMP(ch & 1);
        if (ch + 1 < NC) {
            STSA((ch + 1) & 1);
            asm volatile("cp.async.wait_group 0;" ::: "memory");
            __syncthreads();
        }
    }

    // --- epilogue: bias (+relu) * routing weight, scatter by token ---
    float2 bias[4];
    #pragma unroll
    for (int nt = 0; nt < 4; nt++)
        bias[nt] = *(const float2*)&Bias[e * OUT + n0 + wn * 32 + nt * 8 + (lane & 3) * 2];

    #pragma unroll
    for (int mi = 0; mi < 4; mi++) {
        #pragma unroll
        for (int half = 0; half < 2; half++) {
            int r  = wm * 64 + mi * 16 + (lane >> 2) + half * 8;
            int gi = m0 + r;
            if (gi >= n) continue;
            int   t = s_tok[r];
            float w = s_w[r];
            #pragma unroll
            for (int nt = 0; nt < 4; nt++) {
                float2 v;
                v.x = c[mi][nt][half * 2 + 0] + bias[nt].x;
                v.y = c[mi][nt][half * 2 + 1] + bias[nt].y;
                if constexpr (RELU) {
                    v.x = fmaxf(v.x, 0.0f);
                    v.y = fmaxf(v.y, 0.0f);
                }
                v.x *= w; v.y *= w;
                *(float2*)&Out[(size_t)t * OUT + n0 + wn * 32 + nt * 8 + (lane & 3) * 2] = v;
            }
        }
    }
}

// ---------------- final combine + relu ----------------
__global__ void finalize(float* __restrict__ out) {
    int i = blockIdx.x * blockDim.x + threadIdx.x;
    float4 a = ((const float4*)g_h3a)[i];
    float4 b = ((const float4*)g_h3b)[i];
    float4 v;
    v.x = fmaxf(a.x + b.x, 0.0f);
    v.y = fmaxf(a.y + b.y, 0.0f);
    v.z = fmaxf(a.z + b.z, 0.0f);
    v.w = fmaxf(a.w + b.w, 0.0f);
    ((float4*)out)[i] = v;
}

// ---------------- launch ----------------
extern "C" void kernel_launch(void* const* d_in, const int* in_sizes, int n_in,
                              void* d_out, int out_size) {
    const float*         x  = (const float*)d_in[0];
    const unsigned char* m1 = (const unsigned char*)d_in[1];
    const unsigned char* m2 = (const unsigned char*)d_in[2];
    const unsigned char* m3 = (const unsigned char*)d_in[3];
    const float*         r1 = (const float*)d_in[4];
    const float*         r2 = (const float*)d_in[5];
    const float*         r3 = (const float*)d_in[6];
    const float*         W1 = (const float*)d_in[7];
    const float*         b1 = (const float*)d_in[8];
    const float*         W2 = (const float*)d_in[9];
    const float*         b2 = (const float*)d_in[10];
    const float*         W3 = (const float*)d_in[11];
    const float*         b3 = (const float*)d_in[12];
    float* out = (float*)d_out;

    float *wf1, *wf2, *wf3;
    cudaGetSymbolAddress((void**)&wf1, g_wf1);
    cudaGetSymbolAddress((void**)&wf2, g_wf2);
    cudaGetSymbolAddress((void**)&wf3, g_wf3);

    static bool attr_done = false;
    if (!attr_done) {
        cudaFuncSetAttribute(moe_mma<0, 512, 256, false>,
                             cudaFuncAttributeMaxDynamicSharedMemorySize, SMEM_TOTAL_BYTES);
        cudaFuncSetAttribute(moe_mma<1, 256, 256, false>,
                             cudaFuncAttributeMaxDynamicSharedMemorySize, SMEM_TOTAL_BYTES);
        cudaFuncSetAttribute(moe_mma<2, 256, 512, true>,
                             cudaFuncAttributeMaxDynamicSharedMemorySize, SMEM_TOTAL_BYTES);
        attr_done = true;
    }

    detect_and_zero<<<1, 256>>>(m1);
    route3<<<(3 * NK * T_TOK + 255) / 256, 256>>>(m1, m2, m3, r1, r2, r3);

    constexpr int PREP_N = NE * 64 * 16 * 32 + NE * 32 * 16 * 32 + NE * 32 * 32 * 32;
    prep_all<<<(PREP_N + 255) / 256, 256>>>(W1, W2, W3, wf1, wf2, wf3);

    dim3 g1(T_TOK / 128, 256 / 128, 16);
    dim3 g2(T_TOK / 128, 256 / 128, 16);
    dim3 g3(T_TOK / 128, 512 / 128, 16);
    moe_mma<0, 512, 256, false><<<g1, 256, SMEM_TOTAL_BYTES>>>(x, b1);
    moe_mma<1, 256, 256, false><<<g2, 256, SMEM_TOTAL_BYTES>>>(nullptr, b2);
    moe_mma<2, 256, 512, true ><<<g3, 256, SMEM_TOTAL_BYTES>>>(nullptr, b3);

    finalize<<<(T_TOK * 512 / 4) / 256, 256>>>(out);
}

// round 8
// speedup vs baseline: 1.5964x; 1.2789x over previous
#include <cuda_runtime.h>
#include <cstdint>

#define T_TOK 16384
#define NE 8
#define NK 2

// ---------------- scratch (device globals; no allocation allowed) ----------------
__device__ int   g_maskmode;
__device__ int   g_cnt[3][16];
__device__ int   g_tok[3][16][T_TOK];
__device__ float g_wgt[3][16][T_TOK];
__device__ float g_xr [T_TOK * 512];          // tf32-rounded x
__device__ float g_h1a[T_TOK * 256];
__device__ float g_h1b[T_TOK * 256];
__device__ float g_h1s[T_TOK * 256];          // tf32(h1a+h1b)
__device__ float g_h2a[T_TOK * 256];
__device__ float g_h2b[T_TOK * 256];
__device__ float g_h2s[T_TOK * 256];          // tf32(h2a+h2b)
__device__ float g_h3a[T_TOK * 512];
__device__ float g_h3b[T_TOK * 512];
// fragment-ordered tf32 weights: [e][gs(IN/8)][ntp(OUT/16)][lane32][4]
__device__ float g_wf1[NE * 64 * 16 * 128];   // stage0: IN=512, OUT=256
__device__ float g_wf2[NE * 32 * 16 * 128];   // stage1: IN=256, OUT=256
__device__ float g_wf3[NE * 32 * 32 * 128];   // stage2: IN=256, OUT=512

// ---------------- helpers ----------------
__device__ __forceinline__ uint32_t f2tf(float f) {
    uint32_t u; asm("cvt.rn.tf32.f32 %0, %1;" : "=r"(u) : "f"(f)); return u;
}

__device__ __forceinline__ void mma8(float* c, const uint32_t* a,
                                     uint32_t b0, uint32_t b1) {
    asm volatile(
        "mma.sync.aligned.m16n8k8.row.col.f32.tf32.tf32.f32 "
        "{%0,%1,%2,%3}, {%4,%5,%6,%7}, {%8,%9}, {%0,%1,%2,%3};"
        : "+f"(c[0]), "+f"(c[1]), "+f"(c[2]), "+f"(c[3])
        : "r"(a[0]), "r"(a[1]), "r"(a[2]), "r"(a[3]), "r"(b0), "r"(b1));
}

__device__ __forceinline__ void cp16(uint32_t smem_dst, const void* gsrc) {
    asm volatile("cp.async.cg.shared.global [%0], [%1], 16;"
                 :: "r"(smem_dst), "l"(gsrc));
}

// ---------------- weight pre-transform ----------------
template <int IN, int OUT>
__device__ __forceinline__ void prep_one(int idx, const float* W, float* WF) {
    constexpr int NTPC = OUT / 16;
    constexpr int GS   = IN / 8;
    int lane = idx & 31;
    int rest = idx >> 5;
    int ntp  = rest % NTPC;
    int gs   = (rest / NTPC) % GS;
    int e    = rest / (NTPC * GS);
    int n0 = ntp * 16 + (lane >> 2);
    int k0 = gs * 8 + (lane & 3);
    const float* We = W + (size_t)e * OUT * IN;
    uint4 v;
    v.x = f2tf(We[(size_t)(n0 + 0) * IN + k0]);
    v.y = f2tf(We[(size_t)(n0 + 0) * IN + k0 + 4]);
    v.z = f2tf(We[(size_t)(n0 + 8) * IN + k0]);
    v.w = f2tf(We[(size_t)(n0 + 8) * IN + k0 + 4]);
    ((uint4*)WF)[idx] = v;
}

__global__ void prep_all(const float* __restrict__ W1,
                         const float* __restrict__ W2,
                         const float* __restrict__ W3,
                         float* __restrict__ WF1,
                         float* __restrict__ WF2,
                         float* __restrict__ WF3) {
    constexpr int N1 = NE * 64 * 16 * 32;
    constexpr int N2 = NE * 32 * 16 * 32;
    constexpr int N3 = NE * 32 * 32 * 32;
    int idx = blockIdx.x * blockDim.x + threadIdx.x;
    if (idx < N1) { prep_one<512, 256>(idx, W1, WF1); return; }
    idx -= N1;
    if (idx < N2) { prep_one<256, 256>(idx, W2, WF2); return; }
    idx -= N2;
    if (idx < N3) { prep_one<256, 512>(idx, W3, WF3); }
}

// ---------------- activation rounding / summing ----------------
__global__ void round_x(const float4* __restrict__ a, float4* __restrict__ dst) {
    int i = blockIdx.x * blockDim.x + threadIdx.x;
    float4 v = a[i];
    uint4 u = { f2tf(v.x), f2tf(v.y), f2tf(v.z), f2tf(v.w) };
    dst[i] = *(float4*)&u;
}

__global__ void sum_round(const float4* __restrict__ a, const float4* __restrict__ b,
                          float4* __restrict__ dst) {
    int i = blockIdx.x * blockDim.x + threadIdx.x;
    float4 va = a[i], vb = b[i];
    uint4 u = { f2tf(va.x + vb.x), f2tf(va.y + vb.y),
                f2tf(va.z + vb.z), f2tf(va.w + vb.w) };
    dst[i] = *(float4*)&u;
}

// ---------------- mask dtype detection + counter zeroing ----------------
__global__ void detect_and_zero(const unsigned char* __restrict__ m) {
    __shared__ int bad;
    if (threadIdx.x == 0) bad = 0;
    if (threadIdx.x < 48) ((int*)g_cnt)[threadIdx.x] = 0;
    __syncthreads();
    int t = threadIdx.x;
    #pragma unroll
    for (int k = 0; k < NK; k++) {
        int s = 0;
        #pragma unroll
        for (int e = 0; e < NE; e++)
            s += (m[(e * NK + k) * T_TOK + t] != 0) ? 1 : 0;
        if (s != 1) bad = 1;
    }
    __syncthreads();
    if (threadIdx.x == 0) g_maskmode = bad ? 0 : 1;
}

// ---------------- routing ----------------
__global__ void route3(const unsigned char* __restrict__ m1,
                       const unsigned char* __restrict__ m2,
                       const unsigned char* __restrict__ m3,
                       const float* __restrict__ r1,
                       const float* __restrict__ r2,
                       const float* __restrict__ r3) {
    int tid = blockIdx.x * blockDim.x + threadIdx.x;
    if (tid >= 3 * NK * T_TOK) return;
    int s   = tid / (NK * T_TOK);
    int rem = tid % (NK * T_TOK);
    int k   = rem / T_TOK;
    int t   = rem % T_TOK;
    const unsigned char* m = (s == 0) ? m1 : (s == 1) ? m2 : m3;
    const float*         r = (s == 0) ? r1 : (s == 1) ? r2 : r3;

    int e = 0;
    if (g_maskmode) {
        #pragma unroll
        for (int i = 0; i < NE; i++)
            if (m[(i * NK + k) * T_TOK + t]) e = i;
    } else {
        const int* mi = (const int*)m;
        #pragma unroll
        for (int i = 0; i < NE; i++)
            if (mi[(i * NK + k) * T_TOK + t]) e = i;
    }
    float w = r[t * NK + k];
    int g = k * NE + e;
    int p = atomicAdd(&g_cnt[s][g], 1);
    g_tok[s][g][p] = t;
    g_wgt[s][g][p] = w;
}

// ---------------- tf32 mma.sync gathered expert GEMM ----------------
// BM=128, BN=128, BK=32, 256 threads, 8 warps (2m x 4n), warp 64x32.
// A: raw pre-rounded fp32 via cp.async, 16B-XOR swizzle, conflict-free lds.32.
// B: cp.async from prep'd fragment gmem. 3-deep buffer pipeline, 1 sync/chunk.
// Dyn smem: sA 3x16384 @0 ; sB 3x16384 @49152 ; tok @98304 ; w @98816 ; total 99328
#define SMEM_TOTAL_BYTES 99328

template <int STAGE, int IN, int OUT, bool RELU>
__global__ __launch_bounds__(256, 2)
void moe_mma(const float* __restrict__ Ain,
             const float* __restrict__ Bias) {
    const float* WFg;
    float *O0, *O1;
    if constexpr (STAGE == 0)      { O0 = g_h1a; O1 = g_h1b; WFg = g_wf1; }
    else if constexpr (STAGE == 1) { O0 = g_h2a; O1 = g_h2b; WFg = g_wf2; }
    else                           { O0 = g_h3a; O1 = g_h3b; WFg = g_wf3; }
    constexpr int NTPC = OUT / 16;
    constexpr int NC   = IN / 32;

    const int g  = blockIdx.z;
    const int n  = g_cnt[STAGE][g];
    const int m0 = blockIdx.x * 128;
    if (m0 >= n) return;
    const int e  = g & 7;
    const int n0 = blockIdx.y * 128;
    float* Out = (g >= 8) ? O1 : O0;

    extern __shared__ __align__(16) char dsm[];
    float* sA    = (float*)dsm;                 // [buf3][row128][seg8^swz][4]
    uint4* sB    = (uint4*)(dsm + 49152);       // [buf3][s4][ntp8][lane32]
    int*   s_tok = (int*)(dsm + 98304);
    float* s_w   = (float*)(dsm + 98816);

    const int tid  = threadIdx.x;
    const int wid  = tid >> 5;
    const int lane = tid & 31;
    const int wm   = wid >> 2;
    const int wn   = wid & 3;
    const int l2   = lane >> 2;
    const int l3   = lane & 3;

    if (tid < 128) {
        int gi  = m0 + tid;
        int src = (gi < n) ? gi : (n - 1);
        s_tok[tid] = g_tok[STAGE][g][src];
        s_w[tid]   = (gi < n) ? g_wgt[STAGE][g][src] : 0.0f;
    }
    __syncthreads();

    const uint4* WFe = (const uint4*)(WFg + (size_t)e * (IN / 8) * NTPC * 128);
    const int ntp0 = blockIdx.y * 8;

    // A copy plan: thread covers rows (tid>>3)+{0,32,64,96}, 16B segment tid&7
    const int aseg  = tid & 7;
    const int dseg  = aseg ^ ((tid >> 3) & 7);
    const float* abase[4];
    uint32_t adst[4];
    uint32_t smA = (uint32_t)__cvta_generic_to_shared(sA);
    #pragma unroll
    for (int i = 0; i < 4; i++) {
        int row = (tid >> 3) + i * 32;
        abase[i] = Ain + (size_t)s_tok[row] * IN + aseg * 4;
        adst[i]  = smA + row * 128 + dseg * 16;
    }
    // B copy plan
    const uint4* WFb = WFe + ((size_t)(ntp0 + wid)) * 32 + lane;
    uint32_t smB = (uint32_t)__cvta_generic_to_shared(sB);

    auto ISSUE = [&](int ch, int buf) {
        #pragma unroll
        for (int i = 0; i < 4; i++)
            cp16(adst[i] + buf * 16384, abase[i] + ch * 32);
        #pragma unroll
        for (int i = 0; i < 4; i++)
            cp16(smB + buf * 16384 + (i * 256 + tid) * 16,
                 WFb + (size_t)(ch * 4 + i) * NTPC * 32);
        asm volatile("cp.async.commit_group;" ::: "memory");
    };

    float c[4][4][4];
    #pragma unroll
    for (int a = 0; a < 4; a++)
        #pragma unroll
        for (int b = 0; b < 4; b++)
            #pragma unroll
            for (int d = 0; d < 4; d++) c[a][b][d] = 0.0f;

    auto COMP = [&](int buf) {
        const float* Ab = sA + buf * 4096;
        const uint4* Bb = sB + buf * 1024;
        #pragma unroll
        for (int s = 0; s < 4; s++) {
            const int seg0 = ((s * 2)     ^ l2) * 4 + l3;
            const int seg2 = ((s * 2 + 1) ^ l2) * 4 + l3;
            uint32_t a[4][4];
            #pragma unroll
            for (int mi = 0; mi < 4; mi++) {
                const int rb = (wm * 64 + mi * 16 + l2) * 32;
                a[mi][0] = __float_as_uint(Ab[rb + seg0]);
                a[mi][1] = __float_as_uint(Ab[rb + 256 + seg0]);
                a[mi][2] = __float_as_uint(Ab[rb + seg2]);
                a[mi][3] = __float_as_uint(Ab[rb + 256 + seg2]);
            }
            uint4 b0 = Bb[s * 256 + (wn * 2 + 0) * 32 + lane];
            uint4 b1 = Bb[s * 256 + (wn * 2 + 1) * 32 + lane];
            #pragma unroll
            for (int mi = 0; mi < 4; mi++) {
                mma8(c[mi][0], a[mi], b0.x, b0.y);
                mma8(c[mi][1], a[mi], b0.z, b0.w);
                mma8(c[mi][2], a[mi], b1.x, b1.y);
                mma8(c[mi][3], a[mi], b1.z, b1.w);
            }
        }
    };

    // 3-deep pipeline
    ISSUE(0, 0);
    ISSUE(1, 1);
    asm volatile("cp.async.wait_group 1;" ::: "memory");
    __syncthreads();
    int buf = 0;
    for (int ch = 0; ch < NC; ch++) {
        COMP(buf);
        if (ch + 2 < NC) {
            int nb = buf + 2; if (nb >= 3) nb -= 3;
            ISSUE(ch + 2, nb);
            asm volatile("cp.async.wait_group 1;" ::: "memory");
            __syncthreads();
        } else if (ch + 1 < NC) {
            asm volatile("cp.async.wait_group 0;" ::: "memory");
            __syncthreads();
        }
        if (++buf == 3) buf = 0;
    }

    // --- epilogue: bias (+relu) * routing weight, scatter by token ---
    float2 bias[4];
    #pragma unroll
    for (int nt = 0; nt < 4; nt++)
        bias[nt] = *(const float2*)&Bias[e * OUT + n0 + wn * 32 + nt * 8 + l3 * 2];

    #pragma unroll
    for (int mi = 0; mi < 4; mi++) {
        #pragma unroll
        for (int half = 0; half < 2; half++) {
            int r  = wm * 64 + mi * 16 + l2 + half * 8;
            int gi = m0 + r;
            if (gi >= n) continue;
            int   t = s_tok[r];
            float w = s_w[r];
            #pragma unroll
            for (int nt = 0; nt < 4; nt++) {
                float2 v;
                v.x = c[mi][nt][half * 2 + 0] + bias[nt].x;
                v.y = c[mi][nt][half * 2 + 1] + bias[nt].y;
                if constexpr (RELU) {
                    v.x = fmaxf(v.x, 0.0f);
                    v.y = fmaxf(v.y, 0.0f);
                }
                v.x *= w; v.y *= w;
                *(float2*)&Out[(size_t)t * OUT + n0 + wn * 32 + nt * 8 + l3 * 2] = v;
            }
        }
    }
}

// ---------------- final combine + relu ----------------
__global__ void finalize(float* __restrict__ out) {
    int i = blockIdx.x * blockDim.x + threadIdx.x;
    float4 a = ((const float4*)g_h3a)[i];
    float4 b = ((const float4*)g_h3b)[i];
    float4 v;
    v.x = fmaxf(a.x + b.x, 0.0f);
    v.y = fmaxf(a.y + b.y, 0.0f);
    v.z = fmaxf(a.z + b.z, 0.0f);
    v.w = fmaxf(a.w + b.w, 0.0f);
    ((float4*)out)[i] = v;
}

// ---------------- launch ----------------
extern "C" void kernel_launch(void* const* d_in, const int* in_sizes, int n_in,
                              void* d_out, int out_size) {
    const float*         x  = (const float*)d_in[0];
    const unsigned char* m1 = (const unsigned char*)d_in[1];
    const unsigned char* m2 = (const unsigned char*)d_in[2];
    const unsigned char* m3 = (const unsigned char*)d_in[3];
    const float*         r1 = (const float*)d_in[4];
    const float*         r2 = (const float*)d_in[5];
    const float*         r3 = (const float*)d_in[6];
    const float*         W1 = (const float*)d_in[7];
    const float*         b1 = (const float*)d_in[8];
    const float*         W2 = (const float*)d_in[9];
    const float*         b2 = (const float*)d_in[10];
    const float*         W3 = (const float*)d_in[11];
    const float*         b3 = (const float*)d_in[12];
    float* out = (float*)d_out;

    float *wf1, *wf2, *wf3, *xr, *h1a, *h1b, *h1s, *h2a, *h2b, *h2s;
    cudaGetSymbolAddress((void**)&wf1, g_wf1);
    cudaGetSymbolAddress((void**)&wf2, g_wf2);
    cudaGetSymbolAddress((void**)&wf3, g_wf3);
    cudaGetSymbolAddress((void**)&xr,  g_xr);
    cudaGetSymbolAddress((void**)&h1a, g_h1a);
    cudaGetSymbolAddress((void**)&h1b, g_h1b);
    cudaGetSymbolAddress((void**)&h1s, g_h1s);
    cudaGetSymbolAddress((void**)&h2a, g_h2a);
    cudaGetSymbolAddress((void**)&h2b, g_h2b);
    cudaGetSymbolAddress((void**)&h2s, g_h2s);

    static bool attr_done = false;
    if (!attr_done) {
        cudaFuncSetAttribute(moe_mma<0, 512, 256, false>,
                             cudaFuncAttributeMaxDynamicSharedMemorySize, SMEM_TOTAL_BYTES);
        cudaFuncSetAttribute(moe_mma<1, 256, 256, false>,
                             cudaFuncAttributeMaxDynamicSharedMemorySize, SMEM_TOTAL_BYTES);
        cudaFuncSetAttribute(moe_mma<2, 256, 512, true>,
                             cudaFuncAttributeMaxDynamicSharedMemorySize, SMEM_TOTAL_BYTES);
        attr_done = true;
    }

    detect_and_zero<<<1, 256>>>(m1);
    route3<<<(3 * NK * T_TOK + 255) / 256, 256>>>(m1, m2, m3, r1, r2, r3);

    constexpr int PREP_N = NE * 64 * 16 * 32 + NE * 32 * 16 * 32 + NE * 32 * 32 * 32;
    prep_all<<<(PREP_N + 255) / 256, 256>>>(W1, W2, W3, wf1, wf2, wf3);
    round_x<<<(T_TOK * 512 / 4) / 256, 256>>>((const float4*)x, (float4*)xr);

    dim3 g1(T_TOK / 128, 256 / 128, 16);
    dim3 g2(T_TOK / 128, 256 / 128, 16);
    dim3 g3(T_TOK / 128, 512 / 128, 16);

    moe_mma<0, 512, 256, false><<<g1, 256, SMEM_TOTAL_BYTES>>>(xr, b1);
    sum_round<<<(T_TOK * 256 / 4) / 256, 256>>>((const float4*)h1a, (const float4*)h1b, (float4*)h1s);
    moe_mma<1, 256, 256, false><<<g2, 256, SMEM_TOTAL_BYTES>>>(h1s, b2);
    sum_round<<<(T_TOK * 256 / 4) / 256, 256>>>((const float4*)h2a, (const float4*)h2b, (float4*)h2s);
    moe_mma<2, 256, 512, true ><<<g3, 256, SMEM_TOTAL_BYTES>>>(h2s, b3);

    finalize<<<(T_TOK * 512 / 4) / 256, 256>>>(out);
}

// round 9
// speedup vs baseline: 2.1986x; 1.3772x over previous
#include <cuda_runtime.h>
#include <cuda_fp16.h>
#include <cstdint>

#define T_TOK 16384
#define NE 8
#define NK 2

// ---------------- scratch (device globals; no allocation allowed) ----------------
__device__ int   g_maskmode;
__device__ int   g_cnt[3][16];
__device__ int   g_tok[3][16][T_TOK];
__device__ float g_wgt[3][16][T_TOK];
__device__ uint32_t g_xr [T_TOK * 512 / 2];    // fp16-rounded x (packed half2)
__device__ float g_h1a[T_TOK * 256];
__device__ float g_h1b[T_TOK * 256];
__device__ uint32_t g_h1s[T_TOK * 256 / 2];    // fp16(h1a+h1b)
__device__ float g_h2a[T_TOK * 256];
__device__ float g_h2b[T_TOK * 256];
__device__ uint32_t g_h2s[T_TOK * 256 / 2];    // fp16(h2a+h2b)
__device__ float g_h3a[T_TOK * 512];
__device__ float g_h3b[T_TOK * 512];
// fragment-ordered fp16 weights: [e][gs(IN/16)][ntp(OUT/16)][lane32][uint4]
__device__ uint4 g_wf1[NE * 32 * 16 * 32];     // stage0: IN=512, OUT=256
__device__ uint4 g_wf2[NE * 16 * 16 * 32];     // stage1: IN=256, OUT=256
__device__ uint4 g_wf3[NE * 16 * 32 * 32];     // stage2: IN=256, OUT=512

// ---------------- helpers ----------------
__device__ __forceinline__ uint32_t pack2(float a, float b) {
    __half2 h = __floats2half2_rn(a, b);
    return *(uint32_t*)&h;
}

__device__ __forceinline__ void mma16(float* c, const uint32_t* a,
                                      uint32_t b0, uint32_t b1) {
    asm volatile(
        "mma.sync.aligned.m16n8k16.row.col.f32.f16.f16.f32 "
        "{%0,%1,%2,%3}, {%4,%5,%6,%7}, {%8,%9}, {%0,%1,%2,%3};"
        : "+f"(c[0]), "+f"(c[1]), "+f"(c[2]), "+f"(c[3])
        : "r"(a[0]), "r"(a[1]), "r"(a[2]), "r"(a[3]), "r"(b0), "r"(b1));
}

__device__ __forceinline__ void cp16(uint32_t smem_dst, const void* gsrc) {
    asm volatile("cp.async.cg.shared.global [%0], [%1], 16;"
                 :: "r"(smem_dst), "l"(gsrc));
}

// ---------------- weight pre-transform (fp16 m16n8k16 B fragments) ----------------
template <int IN, int OUT>
__device__ __forceinline__ void prep_one(int idx, const float* W, uint4* WF) {
    constexpr int NTPP = OUT / 16;
    constexpr int GS   = IN / 16;
    int lane = idx & 31;
    int rest = idx >> 5;
    int ntp  = rest % NTPP;
    int gs   = (rest / NTPP) % GS;
    int e    = rest / (NTPP * GS);
    int n0 = ntp * 16 + (lane >> 2);
    int k0 = gs * 16 + (lane & 3) * 2;
    const float* We = W + (size_t)e * OUT * IN;
    uint4 v;
    v.x = pack2(We[(size_t)(n0 + 0) * IN + k0],     We[(size_t)(n0 + 0) * IN + k0 + 1]);
    v.y = pack2(We[(size_t)(n0 + 0) * IN + k0 + 8], We[(size_t)(n0 + 0) * IN + k0 + 9]);
    v.z = pack2(We[(size_t)(n0 + 8) * IN + k0],     We[(size_t)(n0 + 8) * IN + k0 + 1]);
    v.w = pack2(We[(size_t)(n0 + 8) * IN + k0 + 8], We[(size_t)(n0 + 8) * IN + k0 + 9]);
    WF[idx] = v;
}

__global__ void prep_all(const float* __restrict__ W1,
                         const float* __restrict__ W2,
                         const float* __restrict__ W3,
                         uint4* __restrict__ WF1,
                         uint4* __restrict__ WF2,
                         uint4* __restrict__ WF3) {
    constexpr int N1 = NE * 32 * 16 * 32;
    constexpr int N2 = NE * 16 * 16 * 32;
    constexpr int N3 = NE * 16 * 32 * 32;
    int idx = blockIdx.x * blockDim.x + threadIdx.x;
    if (idx < N1) { prep_one<512, 256>(idx, W1, WF1); return; }
    idx -= N1;
    if (idx < N2) { prep_one<256, 256>(idx, W2, WF2); return; }
    idx -= N2;
    if (idx < N3) { prep_one<256, 512>(idx, W3, WF3); }
}

// ---------------- activation rounding / summing (fp32 math, fp16 store) ----------------
__global__ void round_x(const float4* __restrict__ a, uint4* __restrict__ dst) {
    int i = blockIdx.x * blockDim.x + threadIdx.x;
    float4 v0 = a[2 * i], v1 = a[2 * i + 1];
    uint4 u = { pack2(v0.x, v0.y), pack2(v0.z, v0.w),
                pack2(v1.x, v1.y), pack2(v1.z, v1.w) };
    dst[i] = u;
}

__global__ void sum_round(const float4* __restrict__ a, const float4* __restrict__ b,
                          uint4* __restrict__ dst) {
    int i = blockIdx.x * blockDim.x + threadIdx.x;
    float4 a0 = a[2 * i], a1 = a[2 * i + 1];
    float4 b0 = b[2 * i], b1 = b[2 * i + 1];
    uint4 u = { pack2(a0.x + b0.x, a0.y + b0.y), pack2(a0.z + b0.z, a0.w + b0.w),
                pack2(a1.x + b1.x, a1.y + b1.y), pack2(a1.z + b1.z, a1.w + b1.w) };
    dst[i] = u;
}

// ---------------- mask dtype detection + counter zeroing ----------------
__global__ void detect_and_zero(const unsigned char* __restrict__ m) {
    __shared__ int bad;
    if (threadIdx.x == 0) bad = 0;
    if (threadIdx.x < 48) ((int*)g_cnt)[threadIdx.x] = 0;
    __syncthreads();
    int t = threadIdx.x;
    #pragma unroll
    for (int k = 0; k < NK; k++) {
        int s = 0;
        #pragma unroll
        for (int e = 0; e < NE; e++)
            s += (m[(e * NK + k) * T_TOK + t] != 0) ? 1 : 0;
        if (s != 1) bad = 1;
    }
    __syncthreads();
    if (threadIdx.x == 0) g_maskmode = bad ? 0 : 1;
}

// ---------------- routing ----------------
__global__ void route3(const unsigned char* __restrict__ m1,
                       const unsigned char* __restrict__ m2,
                       const unsigned char* __restrict__ m3,
                       const float* __restrict__ r1,
                       const float* __restrict__ r2,
                       const float* __restrict__ r3) {
    int tid = blockIdx.x * blockDim.x + threadIdx.x;
    if (tid >= 3 * NK * T_TOK) return;
    int s   = tid / (NK * T_TOK);
    int rem = tid % (NK * T_TOK);
    int k   = rem / T_TOK;
    int t   = rem % T_TOK;
    const unsigned char* m = (s == 0) ? m1 : (s == 1) ? m2 : m3;
    const float*         r = (s == 0) ? r1 : (s == 1) ? r2 : r3;

    int e = 0;
    if (g_maskmode) {
        #pragma unroll
        for (int i = 0; i < NE; i++)
            if (m[(i * NK + k) * T_TOK + t]) e = i;
    } else {
        const int* mi = (const int*)m;
        #pragma unroll
        for (int i = 0; i < NE; i++)
            if (mi[(i * NK + k) * T_TOK + t]) e = i;
    }
    float w = r[t * NK + k];
    int g = k * NE + e;
    int p = atomicAdd(&g_cnt[s][g], 1);
    g_tok[s][g][p] = t;
    g_wgt[s][g][p] = w;
}

// ---------------- fp16 mma.sync gathered expert GEMM ----------------
// BM=128, BN=128, BK=64 (4 k16 steps), 256 threads, 8 warps (2m x 4n), warp 64x32.
// A: pre-rounded fp16 via cp.async, 16B-XOR swizzle (row 128B), conflict-free lds.32.
// B: cp.async from prep'd fp16 fragment gmem. 3-deep pipeline, 1 sync/chunk.
// Dyn smem: sA 3x16384 @0 ; sB 3x16384 @49152 ; tok @98304 ; w @98816 ; total 99328
#define SMEM_TOTAL_BYTES 99328

template <int STAGE, int IN, int OUT, bool RELU>
__global__ __launch_bounds__(256, 2)
void moe_mma(const void* __restrict__ Ain,
             const float* __restrict__ Bias) {
    const uint4* WFg;
    float *O0, *O1;
    if constexpr (STAGE == 0)      { O0 = g_h1a; O1 = g_h1b; WFg = g_wf1; }
    else if constexpr (STAGE == 1) { O0 = g_h2a; O1 = g_h2b; WFg = g_wf2; }
    else                           { O0 = g_h3a; O1 = g_h3b; WFg = g_wf3; }
    constexpr int NTPP = OUT / 16;
    constexpr int GS   = IN / 16;
    constexpr int NC   = IN / 64;

    const int g  = blockIdx.z;
    const int n  = g_cnt[STAGE][g];
    const int m0 = blockIdx.x * 128;
    if (m0 >= n) return;
    const int e  = g & 7;
    const int n0 = blockIdx.y * 128;
    float* Out = (g >= 8) ? O1 : O0;

    extern __shared__ __align__(16) char dsm[];
    int*   s_tok = (int*)(dsm + 98304);
    float* s_w   = (float*)(dsm + 98816);

    const int tid  = threadIdx.x;
    const int wid  = tid >> 5;
    const int lane = tid & 31;
    const int wm   = wid >> 2;
    const int wn   = wid & 3;
    const int l2   = lane >> 2;
    const int l3   = lane & 3;

    if (tid < 128) {
        int gi  = m0 + tid;
        int src = (gi < n) ? gi : (n - 1);
        s_tok[tid] = g_tok[STAGE][g][src];
        s_w[tid]   = (gi < n) ? g_wgt[STAGE][g][src] : 0.0f;
    }
    __syncthreads();

    const uint4* WFe = WFg + (size_t)e * GS * NTPP * 32;
    const int ntp0 = blockIdx.y * 8;

    // A copy plan: rows (tid>>3)+{0,32,64,96}, 16B segment tid&7 (8 halves)
    const int aseg = tid & 7;
    const int dseg = aseg ^ ((tid >> 3) & 7);
    const char* abase[4];
    uint32_t adst[4];
    uint32_t smA = (uint32_t)__cvta_generic_to_shared(dsm);
    #pragma unroll
    for (int i = 0; i < 4; i++) {
        int row = (tid >> 3) + i * 32;
        abase[i] = (const char*)Ain + ((size_t)s_tok[row] * IN + aseg * 8) * 2;
        adst[i]  = smA + row * 128 + dseg * 16;
    }
    uint32_t smB = (uint32_t)__cvta_generic_to_shared(dsm + 49152);

    auto ISSUE = [&](int ch, int buf) {
        #pragma unroll
        for (int i = 0; i < 4; i++)
            cp16(adst[i] + buf * 16384, abase[i] + ch * 128);
        #pragma unroll
        for (int i = 0; i < 4; i++) {
            int f  = tid + i * 256;           // [s4][ntp8][lane32]
            int bs = f >> 8;
            int bp = (f >> 5) & 7;
            int bl = f & 31;
            cp16(smB + buf * 16384 + f * 16,
                 WFe + ((size_t)(ch * 4 + bs) * NTPP + ntp0 + bp) * 32 + bl);
        }
        asm volatile("cp.async.commit_group;" ::: "memory");
    };

    float c[4][4][4];
    #pragma unroll
    for (int a = 0; a < 4; a++)
        #pragma unroll
        for (int b = 0; b < 4; b++)
            #pragma unroll
            for (int d = 0; d < 4; d++) c[a][b][d] = 0.0f;

    auto COMP = [&](int buf) {
        const char* Ab = dsm + buf * 16384;
        const uint4* Bb = (const uint4*)(dsm + 49152 + buf * 16384);
        #pragma unroll
        for (int s = 0; s < 4; s++) {
            const int off0 = (((2 * s)     ^ l2) << 4) + l3 * 4;
            const int off1 = (((2 * s + 1) ^ l2) << 4) + l3 * 4;
            uint32_t a[4][4];
            #pragma unroll
            for (int mi = 0; mi < 4; mi++) {
                const char* rp = Ab + (wm * 64 + mi * 16 + l2) * 128;
                a[mi][0] = *(const uint32_t*)(rp + off0);
                a[mi][1] = *(const uint32_t*)(rp + 1024 + off0);
                a[mi][2] = *(const uint32_t*)(rp + off1);
                a[mi][3] = *(const uint32_t*)(rp + 1024 + off1);
            }
            uint4 b0 = Bb[s * 256 + (wn * 2 + 0) * 32 + lane];
            uint4 b1 = Bb[s * 256 + (wn * 2 + 1) * 32 + lane];
            #pragma unroll
            for (int mi = 0; mi < 4; mi++) {
                mma16(c[mi][0], a[mi], b0.x, b0.y);
                mma16(c[mi][1], a[mi], b0.z, b0.w);
                mma16(c[mi][2], a[mi], b1.x, b1.y);
                mma16(c[mi][3], a[mi], b1.z, b1.w);
            }
        }
    };

    // 3-deep pipeline
    ISSUE(0, 0);
    ISSUE(1, 1);
    asm volatile("cp.async.wait_group 1;" ::: "memory");
    __syncthreads();
    int buf = 0;
    for (int ch = 0; ch < NC; ch++) {
        COMP(buf);
        if (ch + 2 < NC) {
            int nb = buf + 2; if (nb >= 3) nb -= 3;
            ISSUE(ch + 2, nb);
            asm volatile("cp.async.wait_group 1;" ::: "memory");
            __syncthreads();
        } else if (ch + 1 < NC) {
            asm volatile("cp.async.wait_group 0;" ::: "memory");
            __syncthreads();
        }
        if (++buf == 3) buf = 0;
    }

    // --- epilogue: bias (+relu) * routing weight, scatter by token ---
    float2 bias[4];
    #pragma unroll
    for (int nt = 0; nt < 4; nt++)
        bias[nt] = *(const float2*)&Bias[e * OUT + n0 + wn * 32 + nt * 8 + l3 * 2];

    #pragma unroll
    for (int mi = 0; mi < 4; mi++) {
        #pragma unroll
        for (int half = 0; half < 2; half++) {
            int r  = wm * 64 + mi * 16 + l2 + half * 8;
            int gi = m0 + r;
            if (gi >= n) continue;
            int   t = s_tok[r];
            float w = s_w[r];
            #pragma unroll
            for (int nt = 0; nt < 4; nt++) {
                float2 v;
                v.x = c[mi][nt][half * 2 + 0] + bias[nt].x;
                v.y = c[mi][nt][half * 2 + 1] + bias[nt].y;
                if constexpr (RELU) {
                    v.x = fmaxf(v.x, 0.0f);
                    v.y = fmaxf(v.y, 0.0f);
                }
                v.x *= w; v.y *= w;
                *(float2*)&Out[(size_t)t * OUT + n0 + wn * 32 + nt * 8 + l3 * 2] = v;
            }
        }
    }
}

// ---------------- final combine + relu ----------------
__global__ void finalize(float* __restrict__ out) {
    int i = blockIdx.x * blockDim.x + threadIdx.x;
    float4 a = ((const float4*)g_h3a)[i];
    float4 b = ((const float4*)g_h3b)[i];
    float4 v;
    v.x = fmaxf(a.x + b.x, 0.0f);
    v.y = fmaxf(a.y + b.y, 0.0f);
    v.z = fmaxf(a.z + b.z, 0.0f);
    v.w = fmaxf(a.w + b.w, 0.0f);
    ((float4*)out)[i] = v;
}

// ---------------- launch ----------------
extern "C" void kernel_launch(void* const* d_in, const int* in_sizes, int n_in,
                              void* d_out, int out_size) {
    const float*         x  = (const float*)d_in[0];
    const unsigned char* m1 = (const unsigned char*)d_in[1];
    const unsigned char* m2 = (const unsigned char*)d_in[2];
    const unsigned char* m3 = (const unsigned char*)d_in[3];
    const float*         r1 = (const float*)d_in[4];
    const float*         r2 = (const float*)d_in[5];
    const float*         r3 = (const float*)d_in[6];
    const float*         W1 = (const float*)d_in[7];
    const float*         b1 = (const float*)d_in[8];
    const float*         W2 = (const float*)d_in[9];
    const float*         b2 = (const float*)d_in[10];
    const float*         W3 = (const float*)d_in[11];
    const float*         b3 = (const float*)d_in[12];
    float* out = (float*)d_out;

    uint4 *wf1, *wf2, *wf3;
    void *xr, *h1a, *h1b, *h1s, *h2a, *h2b, *h2s;
    cudaGetSymbolAddress((void**)&wf1, g_wf1);
    cudaGetSymbolAddress((void**)&wf2, g_wf2);
    cudaGetSymbolAddress((void**)&wf3, g_wf3);
    cudaGetSymbolAddress(&xr,  g_xr);
    cudaGetSymbolAddress(&h1a, g_h1a);
    cudaGetSymbolAddress(&h1b, g_h1b);
    cudaGetSymbolAddress(&h1s, g_h1s);
    cudaGetSymbolAddress(&h2a, g_h2a);
    cudaGetSymbolAddress(&h2b, g_h2b);
    cudaGetSymbolAddress(&h2s, g_h2s);

    static bool attr_done = false;
    if (!attr_done) {
        cudaFuncSetAttribute(moe_mma<0, 512, 256, false>,
                             cudaFuncAttributeMaxDynamicSharedMemorySize, SMEM_TOTAL_BYTES);
        cudaFuncSetAttribute(moe_mma<1, 256, 256, false>,
                             cudaFuncAttributeMaxDynamicSharedMemorySize, SMEM_TOTAL_BYTES);
        cudaFuncSetAttribute(moe_mma<2, 256, 512, true>,
                             cudaFuncAttributeMaxDynamicSharedMemorySize, SMEM_TOTAL_BYTES);
        attr_done = true;
    }

    detect_and_zero<<<1, 256>>>(m1);
    route3<<<(3 * NK * T_TOK + 255) / 256, 256>>>(m1, m2, m3, r1, r2, r3);

    constexpr int PREP_N = NE * 32 * 16 * 32 + NE * 16 * 16 * 32 + NE * 16 * 32 * 32;
    prep_all<<<(PREP_N + 255) / 256, 256>>>(W1, W2, W3, wf1, wf2, wf3);
    round_x<<<(T_TOK * 512 / 8) / 256, 256>>>((const float4*)x, (uint4*)xr);

    dim3 g1(T_TOK / 128, 256 / 128, 16);
    dim3 g2(T_TOK / 128, 256 / 128, 16);
    dim3 g3(T_TOK / 128, 512 / 128, 16);

    moe_mma<0, 512, 256, false><<<g1, 256, SMEM_TOTAL_BYTES>>>(xr, b1);
    sum_round<<<(T_TOK * 256 / 8) / 256, 256>>>((const float4*)h1a, (const float4*)h1b, (uint4*)h1s);
    moe_mma<1, 256, 256, false><<<g2, 256, SMEM_TOTAL_BYTES>>>(h1s, b2);
    sum_round<<<(T_TOK * 256 / 8) / 256, 256>>>((const float4*)h2a, (const float4*)h2b, (uint4*)h2s);
    moe_mma<2, 256, 512, true ><<<g3, 256, SMEM_TOTAL_BYTES>>>(h2s, b3);

    finalize<<<(T_TOK * 512 / 4) / 256, 256>>>(out);
}